// round 6
// baseline (speedup 1.0000x reference)
#include <cuda_runtime.h>
#include <math.h>
#include <stdint.h>

#define N_ENT 1024
#define BATCH 128
#define T_TOK 64
#define P_TOK 49
#define D_IN 768
#define H_DIM 512
#define N_EXP 8

// ----------------------------- static scratch ------------------------------
__device__ float g_etc[N_ENT * H_DIM];
__device__ float g_eic[N_ENT * H_DIM];
__device__ float g_mtc[BATCH * H_DIM];
__device__ float g_mic[BATCH * H_DIM];
__device__ float g_ett[N_ENT * T_TOK * H_DIM];
__device__ float g_eit[N_ENT * P_TOK * H_DIM];
__device__ float g_mtt[BATCH * T_TOK * H_DIM];
__device__ float g_mit[BATCH * P_TOK * H_DIM];

__device__ float g_eti_m[N_ENT * 50 * H_DIM];
__device__ float g_mti_m[BATCH * 50 * H_DIM];
__device__ float g_eit_m[N_ENT * 65 * H_DIM];
__device__ float g_mit_m[BATCH * 65 * H_DIM];

__device__ int2   g_eidx[4][N_ENT];
__device__ float2 g_ew[4][N_ENT];

__device__ float g_ctx0[N_ENT * H_DIM];
__device__ float g_ctx1[BATCH * H_DIM];
__device__ float g_ctx2[N_ENT * H_DIM];
__device__ float g_ctx3[BATCH * H_DIM];

__device__ float g_fe_ti[N_ENT * H_DIM];
__device__ float g_fm_ti[BATCH * H_DIM];
__device__ float g_fe_it[N_ENT * H_DIM];
__device__ float g_fm_it[BATCH * H_DIM];

__device__ float g_wc_text[D_IN * N_EXP];
__device__ float g_wc_img[D_IN * N_EXP];
__device__ float g_bterm[2 * N_EXP];

// ------------------------------ tf32 helpers -------------------------------
__device__ __forceinline__ void split_tf32(float x, uint32_t& hi, uint32_t& lo)
{
    asm("cvt.rna.tf32.f32 %0, %1;" : "=r"(hi) : "f"(x));
    float r = x - __uint_as_float(hi);
    asm("cvt.rna.tf32.f32 %0, %1;" : "=r"(lo) : "f"(r));
}

__device__ __forceinline__ void mma8(float* c, const uint32_t* a, const uint32_t* b)
{
    asm volatile(
        "mma.sync.aligned.m16n8k8.row.col.f32.tf32.tf32.f32 "
        "{%0,%1,%2,%3}, {%4,%5,%6,%7}, {%8,%9}, {%0,%1,%2,%3};"
        : "+f"(c[0]), "+f"(c[1]), "+f"(c[2]), "+f"(c[3])
        : "r"(a[0]), "r"(a[1]), "r"(a[2]), "r"(a[3]), "r"(b[0]), "r"(b[1]));
}

#define AS_STR 20
#define BS_STR 132

// ----------------- proj (3xTF32): C[M,512]=A[M,768]@W+bias -----------------
// Block 128x128, BK=16, double-buffered smem (1 barrier per K tile).
#define P_ASZ (128 * AS_STR)
#define P_BSZ (16 * BS_STR)
#define P_SMEM_BYTES ((2 * P_ASZ * 2 + 2 * P_BSZ * 2) * 4)

__global__ __launch_bounds__(256) void proj_tc(
    const float* __restrict__ A, const float* __restrict__ W,
    const float* __restrict__ bias, float* __restrict__ C, int M)
{
    extern __shared__ uint32_t dyn[];
    uint32_t* AsH = dyn;                    // [2][P_ASZ]
    uint32_t* AsL = AsH + 2 * P_ASZ;
    uint32_t* BsH = AsL + 2 * P_ASZ;        // [2][P_BSZ]
    uint32_t* BsL = BsH + 2 * P_BSZ;

    const int tid = threadIdx.x;
    const int row0 = blockIdx.x * 128;
    const int col0 = blockIdx.y * 128;
    const int warp = tid >> 5, lane = tid & 31;
    const int wm = warp >> 2, wn = warp & 3;
    const int gid = lane >> 2, tig = lane & 3;

    const int ar  = tid >> 2;
    const int ac4 = (tid & 3) * 4;
    const int bk  = tid >> 5;
    const int bc4 = (tid & 31) * 4;

    float acc[4][4][4];
#pragma unroll
    for (int a = 0; a < 4; a++)
#pragma unroll
        for (int b = 0; b < 4; b++)
#pragma unroll
            for (int c = 0; c < 4; c++) acc[a][b][c] = 0.f;

    float4 pa[2], pb[2];
    const float* Abase = A + (size_t)row0 * D_IN;

    auto load_tiles = [&](int k0) {
        pa[0] = *(const float4*)(Abase + (size_t)ar * D_IN + k0 + ac4);
        pa[1] = *(const float4*)(Abase + (size_t)(ar + 64) * D_IN + k0 + ac4);
        pb[0] = *(const float4*)(W + (size_t)(k0 + bk) * H_DIM + col0 + bc4);
        pb[1] = *(const float4*)(W + (size_t)(k0 + bk + 8) * H_DIM + col0 + bc4);
    };
    auto store_tiles = [&](int buf) {
        uint32_t* aH = AsH + buf * P_ASZ; uint32_t* aL = AsL + buf * P_ASZ;
        uint32_t* bH = BsH + buf * P_BSZ; uint32_t* bL = BsL + buf * P_BSZ;
#pragma unroll
        for (int p = 0; p < 2; p++) {
            float v[4] = {pa[p].x, pa[p].y, pa[p].z, pa[p].w};
            uint4 h, l;
            split_tf32(v[0], h.x, l.x); split_tf32(v[1], h.y, l.y);
            split_tf32(v[2], h.z, l.z); split_tf32(v[3], h.w, l.w);
            int base = (ar + p * 64) * AS_STR + ac4;
            *(uint4*)&aH[base] = h; *(uint4*)&aL[base] = l;

            float u[4] = {pb[p].x, pb[p].y, pb[p].z, pb[p].w};
            split_tf32(u[0], h.x, l.x); split_tf32(u[1], h.y, l.y);
            split_tf32(u[2], h.z, l.z); split_tf32(u[3], h.w, l.w);
            int bbase = (bk + p * 8) * BS_STR + bc4;
            *(uint4*)&bH[bbase] = h; *(uint4*)&bL[bbase] = l;
        }
    };

    load_tiles(0);
    store_tiles(0);
    __syncthreads();

    const int NKB = D_IN / 16;
    for (int kb = 0; kb < NKB; kb++) {
        if (kb + 1 < NKB) load_tiles((kb + 1) * 16);
        const int cur = kb & 1;
        const uint32_t* aH = AsH + cur * P_ASZ; const uint32_t* aL = AsL + cur * P_ASZ;
        const uint32_t* bH = BsH + cur * P_BSZ; const uint32_t* bL = BsL + cur * P_BSZ;
#pragma unroll
        for (int kk = 0; kk < 16; kk += 8) {
            uint32_t ah[4][4], al[4][4], bh[4][2], bl[4][2];
#pragma unroll
            for (int mt = 0; mt < 4; mt++) {
                int b0 = (wm * 64 + mt * 16 + gid) * AS_STR + kk + tig;
                ah[mt][0] = aH[b0];     ah[mt][1] = aH[b0 + 8 * AS_STR];
                ah[mt][2] = aH[b0 + 4]; ah[mt][3] = aH[b0 + 8 * AS_STR + 4];
                al[mt][0] = aL[b0];     al[mt][1] = aL[b0 + 8 * AS_STR];
                al[mt][2] = aL[b0 + 4]; al[mt][3] = aL[b0 + 8 * AS_STR + 4];
            }
#pragma unroll
            for (int nt = 0; nt < 4; nt++) {
                int b0 = (kk + tig) * BS_STR + wn * 32 + nt * 8 + gid;
                bh[nt][0] = bH[b0]; bh[nt][1] = bH[b0 + 4 * BS_STR];
                bl[nt][0] = bL[b0]; bl[nt][1] = bL[b0 + 4 * BS_STR];
            }
#pragma unroll
            for (int mt = 0; mt < 4; mt++)
#pragma unroll
                for (int nt = 0; nt < 4; nt++) mma8(acc[mt][nt], ah[mt], bh[nt]);
#pragma unroll
            for (int mt = 0; mt < 4; mt++)
#pragma unroll
                for (int nt = 0; nt < 4; nt++) mma8(acc[mt][nt], ah[mt], bl[nt]);
#pragma unroll
            for (int mt = 0; mt < 4; mt++)
#pragma unroll
                for (int nt = 0; nt < 4; nt++) mma8(acc[mt][nt], al[mt], bh[nt]);
        }
        if (kb + 1 < NKB) store_tiles((kb + 1) & 1);
        __syncthreads();
    }

#pragma unroll
    for (int mt = 0; mt < 4; mt++) {
        int m = row0 + wm * 64 + mt * 16 + gid;
#pragma unroll
        for (int nt = 0; nt < 4; nt++) {
            int n = col0 + wn * 32 + nt * 8 + tig * 2;
            float2 bv = *(const float2*)(bias + n);
            *(float2*)(C + (size_t)m * H_DIM + n) =
                make_float2(acc[mt][nt][0] + bv.x, acc[mt][nt][1] + bv.y);
            *(float2*)(C + (size_t)(m + 8) * H_DIM + n) =
                make_float2(acc[mt][nt][2] + bv.x, acc[mt][nt][3] + bv.y);
        }
    }
}

// ------- MoE (3xTF32): out = x @ (w0*We[e0]+w1*We[e1]) + combined bias ------
template<int WM>
__global__ __launch_bounds__(256) void moe_tc(
    const float* __restrict__ cls, const float* __restrict__ tok, int S,
    const float* __restrict__ We, const float* __restrict__ be,
    const int2* __restrict__ eidx, const float2* __restrict__ ew,
    float* __restrict__ out)
{
    constexpr int BM = WM * 32;
    constexpr int PF = (BM * 4 + 255) / 256;
    constexpr int ASZ = BM * AS_STR;
    constexpr int BSZ = 16 * BS_STR;

    extern __shared__ uint32_t dyn[];
    uint32_t* AsH = dyn;
    uint32_t* AsL = AsH + 2 * ASZ;
    uint32_t* BsH = AsL + 2 * ASZ;
    uint32_t* BsL = BsH + 2 * BSZ;

    const int i = blockIdx.z;
    const int col0 = blockIdx.x * 128;
    const int2 e = eidx[i];
    const float2 w = ew[i];
    const float* W0 = We + (size_t)e.x * H_DIM * H_DIM;
    const float* W1 = We + (size_t)e.y * H_DIM * H_DIM;

    const int tid = threadIdx.x;
    const int warp = tid >> 5, lane = tid & 31;
    const int wm = warp >> 2, wn = warp & 3;
    const int gid = lane >> 2, tig = lane & 3;
    const int bk = tid >> 5, bc4 = (tid & 31) * 4;

    float acc[WM][4][4];
#pragma unroll
    for (int a = 0; a < WM; a++)
#pragma unroll
        for (int b = 0; b < 4; b++)
#pragma unroll
            for (int c = 0; c < 4; c++) acc[a][b][c] = 0.f;

    float4 pa[PF], pb[2];

    auto load_tiles = [&](int k0) {
#pragma unroll
        for (int p = 0; p < PF; p++) {
            int idx = p * 256 + tid;
            float4 v = make_float4(0.f, 0.f, 0.f, 0.f);
            if (idx < BM * 4) {
                int t = idx >> 2;
                if (t < S) {
                    const float* rp = (t == 0)
                        ? (cls + (size_t)i * H_DIM)
                        : (tok + ((size_t)i * (S - 1) + (t - 1)) * H_DIM);
                    v = *(const float4*)(rp + k0 + (idx & 3) * 4);
                }
            }
            pa[p] = v;
        }
#pragma unroll
        for (int p = 0; p < 2; p++) {
            size_t off = (size_t)(k0 + bk + p * 8) * H_DIM + col0 + bc4;
            float4 v0 = *(const float4*)(W0 + off);
            float4 v1 = *(const float4*)(W1 + off);
            pb[p] = make_float4(w.x * v0.x + w.y * v1.x, w.x * v0.y + w.y * v1.y,
                                w.x * v0.z + w.y * v1.z, w.x * v0.w + w.y * v1.w);
        }
    };
    auto store_tiles = [&](int buf) {
        uint32_t* aH = AsH + buf * ASZ; uint32_t* aL = AsL + buf * ASZ;
        uint32_t* bH = BsH + buf * BSZ; uint32_t* bL = BsL + buf * BSZ;
#pragma unroll
        for (int p = 0; p < PF; p++) {
            int idx = p * 256 + tid;
            if (idx < BM * 4) {
                float v[4] = {pa[p].x, pa[p].y, pa[p].z, pa[p].w};
                uint4 h, l;
                split_tf32(v[0], h.x, l.x); split_tf32(v[1], h.y, l.y);
                split_tf32(v[2], h.z, l.z); split_tf32(v[3], h.w, l.w);
                int base = (idx >> 2) * AS_STR + (idx & 3) * 4;
                *(uint4*)&aH[base] = h; *(uint4*)&aL[base] = l;
            }
        }
#pragma unroll
        for (int p = 0; p < 2; p++) {
            float u[4] = {pb[p].x, pb[p].y, pb[p].z, pb[p].w};
            uint4 h, l;
            split_tf32(u[0], h.x, l.x); split_tf32(u[1], h.y, l.y);
            split_tf32(u[2], h.z, l.z); split_tf32(u[3], h.w, l.w);
            int bbase = (bk + p * 8) * BS_STR + bc4;
            *(uint4*)&bH[bbase] = h; *(uint4*)&bL[bbase] = l;
        }
    };

    load_tiles(0);
    store_tiles(0);
    __syncthreads();

    const int NKB = H_DIM / 16;
    for (int kb = 0; kb < NKB; kb++) {
        if (kb + 1 < NKB) load_tiles((kb + 1) * 16);
        const int cur = kb & 1;
        const uint32_t* aH = AsH + cur * ASZ; const uint32_t* aL = AsL + cur * ASZ;
        const uint32_t* bH = BsH + cur * BSZ; const uint32_t* bL = BsL + cur * BSZ;
#pragma unroll
        for (int kk = 0; kk < 16; kk += 8) {
            uint32_t ah[WM][4], al[WM][4], bh[4][2], bl[4][2];
#pragma unroll
            for (int mt = 0; mt < WM; mt++) {
                int b0 = (wm * WM * 16 + mt * 16 + gid) * AS_STR + kk + tig;
                ah[mt][0] = aH[b0];     ah[mt][1] = aH[b0 + 8 * AS_STR];
                ah[mt][2] = aH[b0 + 4]; ah[mt][3] = aH[b0 + 8 * AS_STR + 4];
                al[mt][0] = aL[b0];     al[mt][1] = aL[b0 + 8 * AS_STR];
                al[mt][2] = aL[b0 + 4]; al[mt][3] = aL[b0 + 8 * AS_STR + 4];
            }
#pragma unroll
            for (int nt = 0; nt < 4; nt++) {
                int b0 = (kk + tig) * BS_STR + wn * 32 + nt * 8 + gid;
                bh[nt][0] = bH[b0]; bh[nt][1] = bH[b0 + 4 * BS_STR];
                bl[nt][0] = bL[b0]; bl[nt][1] = bL[b0 + 4 * BS_STR];
            }
#pragma unroll
            for (int mt = 0; mt < WM; mt++)
#pragma unroll
                for (int nt = 0; nt < 4; nt++) mma8(acc[mt][nt], ah[mt], bh[nt]);
#pragma unroll
            for (int mt = 0; mt < WM; mt++)
#pragma unroll
                for (int nt = 0; nt < 4; nt++) mma8(acc[mt][nt], ah[mt], bl[nt]);
#pragma unroll
            for (int mt = 0; mt < WM; mt++)
#pragma unroll
                for (int nt = 0; nt < 4; nt++) mma8(acc[mt][nt], al[mt], bh[nt]);
        }
        if (kb + 1 < NKB) store_tiles((kb + 1) & 1);
        __syncthreads();
    }

#pragma unroll
    for (int mt = 0; mt < WM; mt++) {
        int t = wm * WM * 16 + mt * 16 + gid;
#pragma unroll
        for (int nt = 0; nt < 4; nt++) {
            int n = col0 + wn * 32 + nt * 8 + tig * 2;
            float b0 = w.x * be[e.x * H_DIM + n]     + w.y * be[e.y * H_DIM + n];
            float b1 = w.x * be[e.x * H_DIM + n + 1] + w.y * be[e.y * H_DIM + n + 1];
            if (t < S)
                *(float2*)(out + ((size_t)i * S + t) * H_DIM + n) =
                    make_float2(acc[mt][nt][0] + b0, acc[mt][nt][1] + b1);
            if (t + 8 < S)
                *(float2*)(out + ((size_t)i * S + t + 8) * H_DIM + n) =
                    make_float2(acc[mt][nt][2] + b0, acc[mt][nt][3] + b1);
        }
    }
}

// --------------------- router weight folding (fp32-exact) ------------------
__global__ void combine_w_kernel(const float* __restrict__ Wt, const float* __restrict__ Wi,
                                 const float* __restrict__ Wr,
                                 float* __restrict__ WcT, float* __restrict__ WcI)
{
    int idx = blockIdx.x * blockDim.x + threadIdx.x;
    if (idx >= D_IN * N_EXP) return;
    int k = idx >> 3, e = idx & 7;
    float st = 0.f, si = 0.f;
    for (int h = 0; h < H_DIM; h++) {
        float wr = Wr[h * N_EXP + e];
        st += Wt[(size_t)k * H_DIM + h] * wr;
        si += Wi[(size_t)k * H_DIM + h] * wr;
    }
    WcT[idx] = st;
    WcI[idx] = si;
}

__global__ void bterm_kernel(const float* __restrict__ bt, const float* __restrict__ bi,
                             const float* __restrict__ Wr, const float* __restrict__ br,
                             float* __restrict__ bterm)
{
    int e = threadIdx.x;
    if (e < N_EXP) {
        float sA = 0.f, sB = 0.f;
        for (int h = 0; h < H_DIM; h++) {
            float wr = Wr[h * N_EXP + e];
            sA += (bi[h] + 64.f * bt[h]) * wr;   // y = [img cls, 64 text tokens]
            sB += (bt[h] + 49.f * bi[h]) * wr;   // y = [text cls, 49 img tokens]
        }
        bterm[e]         = sA / 65.f + br[e];
        bterm[N_EXP + e] = sB / 50.f + br[e];
    }
}

// -------- router from raw inputs: exact fp32 logits -> top2 + weights ------
__global__ __launch_bounds__(256) void router2_kernel(
    const float* __restrict__ cls, const float* __restrict__ tok, int Sm1,
    const float* __restrict__ WcCls, const float* __restrict__ WcTok,
    const float* __restrict__ bt,
    int2* __restrict__ eidx, float2* __restrict__ ew)
{
    const int i = blockIdx.x, tid = threadIdx.x;
    float part[N_EXP];
#pragma unroll
    for (int e = 0; e < N_EXP; e++) part[e] = 0.f;

    for (int c = tid; c < D_IN; c += 256) {
        float s = 0.f;
        for (int t = 0; t < Sm1; t++)
            s += tok[((size_t)i * Sm1 + t) * D_IN + c];
        float cl = cls[(size_t)i * D_IN + c];
#pragma unroll
        for (int e = 0; e < N_EXP; e++)
            part[e] += cl * WcCls[c * N_EXP + e] + s * WcTok[c * N_EXP + e];
    }
#pragma unroll
    for (int o = 16; o; o >>= 1)
#pragma unroll
        for (int e = 0; e < N_EXP; e++)
            part[e] += __shfl_down_sync(0xffffffffu, part[e], o);

    __shared__ float red[8][N_EXP];
    __shared__ float logits[N_EXP];
    const int warp = tid >> 5, lane = tid & 31;
    if (lane == 0)
#pragma unroll
        for (int e = 0; e < N_EXP; e++) red[warp][e] = part[e];
    __syncthreads();
    if (tid < N_EXP) {
        float l = 0.f;
        for (int wq = 0; wq < 8; wq++) l += red[wq][tid];
        logits[tid] = l / (float)(Sm1 + 1) + bt[tid];
    }
    __syncthreads();
    if (tid == 0) {
        int b0 = 0;
        for (int e = 1; e < N_EXP; e++)
            if (logits[e] > logits[b0]) b0 = e;
        int b1 = (b0 == 0) ? 1 : 0;
        for (int e = 0; e < N_EXP; e++)
            if (e != b0 && logits[e] > logits[b1]) b1 = e;
        float e1v = expf(logits[b1] - logits[b0]);
        float inv = 1.0f / (1.0f + e1v);
        eidx[i] = make_int2(b0, b1);
        ew[i] = make_float2(inv, e1v * inv);
    }
}

// ------------------------------ cross attention -----------------------------
__global__ __launch_bounds__(256) void cross_kernel(
    const float* __restrict__ moe_out, int S, float* __restrict__ ctx)
{
    const int i = blockIdx.x;
    __shared__ float cls_s[H_DIM];
    __shared__ float prob[64];
    const int tid = threadIdx.x;
    const float* base = moe_out + (size_t)i * S * H_DIM;

    for (int c = tid; c < H_DIM; c += 256) cls_s[c] = base[c];
    __syncthreads();

    const int nt = S - 1;
    const int warp = tid >> 5, lane = tid & 31;
    for (int s = warp; s < nt; s += 8) {
        const float* trow = base + (size_t)(s + 1) * H_DIM;
        float p = 0.f;
        for (int c = lane; c < H_DIM; c += 32) p += cls_s[c] * trow[c];
#pragma unroll
        for (int o = 16; o; o >>= 1) p += __shfl_down_sync(0xffffffffu, p, o);
        if (lane == 0) prob[s] = p;
    }
    __syncthreads();

    if (tid == 0) {
        float mx = -1e30f;
        for (int s = 0; s < nt; s++) mx = fmaxf(mx, prob[s]);
        float sum = 0.f;
        for (int s = 0; s < nt; s++) { float e = expf(prob[s] - mx); prob[s] = e; sum += e; }
        float inv = 1.0f / sum;
        for (int s = 0; s < nt; s++) prob[s] *= inv;
    }
    __syncthreads();

    for (int c = tid; c < H_DIM; c += 256) {
        float a = 0.f;
        for (int s = 0; s < nt; s++) a += prob[s] * base[(size_t)(s + 1) * H_DIM + c];
        ctx[(size_t)i * H_DIM + c] = a;
    }
}

// --------------------------- gate + residual + LN ---------------------------
__global__ __launch_bounds__(256) void gate_ln_kernel(
    const float* __restrict__ ori, const float* __restrict__ ctx,
    const float* __restrict__ Wg, const float* __restrict__ bg,
    const float* __restrict__ ls, const float* __restrict__ lb,
    float* __restrict__ out, int gate_from_ctx)
{
    const int i = blockIdx.x;
    __shared__ float v[H_DIM];
    __shared__ float red[256];
    const int tid = threadIdx.x;
    const float* orow = ori + (size_t)i * H_DIM;
    const float* crow = ctx + (size_t)i * H_DIM;

    float p = 0.f;
    for (int c = tid; c < H_DIM; c += 256) {
        float gs = gate_from_ctx ? crow[c] : orow[c];
        p += gs * Wg[c];
    }
    red[tid] = p; __syncthreads();
    for (int o = 128; o; o >>= 1) { if (tid < o) red[tid] += red[tid + o]; __syncthreads(); }
    float gate = tanhf(red[0] + bg[0]);
    __syncthreads();

    float sum = 0.f;
    for (int c = tid; c < H_DIM; c += 256) {
        float val = orow[c] * gate + crow[c];
        v[c] = val; sum += val;
    }
    red[tid] = sum; __syncthreads();
    for (int o = 128; o; o >>= 1) { if (tid < o) red[tid] += red[tid + o]; __syncthreads(); }
    float mean = red[0] / (float)H_DIM;
    __syncthreads();

    float var = 0.f;
    for (int c = tid; c < H_DIM; c += 256) { float d = v[c] - mean; var += d * d; }
    red[tid] = var; __syncthreads();
    for (int o = 128; o; o >>= 1) { if (tid < o) red[tid] += red[tid + o]; __syncthreads(); }
    float rstd = rsqrtf(red[0] / (float)H_DIM + 1e-5f);

    for (int c = tid; c < H_DIM; c += 256)
        out[(size_t)i * H_DIM + c] = (v[c] - mean) * rstd * ls[c] + lb[c];
}

// -------------------------------- final score -------------------------------
__global__ __launch_bounds__(256) void score_kernel(
    const float* __restrict__ mti, const float* __restrict__ eti,
    const float* __restrict__ mit, const float* __restrict__ eit,
    float* __restrict__ out)
{
    __shared__ float As[8][64];
    __shared__ float Bs[8][64];
    const int n0 = blockIdx.x * 64;
    const int b0 = blockIdx.y * 64;
    const int tid = threadIdx.x;
    const int tx = tid & 15, ty = tid >> 4;
    const int lrow = tid >> 2, lcol = (tid & 3) * 2;

    float acc[4][4];
#pragma unroll
    for (int q = 0; q < 4; q++)
#pragma unroll
        for (int r = 0; r < 4; r++) acc[q][r] = 0.f;

#pragma unroll
    for (int pass = 0; pass < 2; pass++) {
        const float* A = pass ? mit : mti;
        const float* B = pass ? eit : eti;
        for (int k0 = 0; k0 < H_DIM; k0 += 8) {
            float2 av = *(const float2*)(A + (size_t)(b0 + lrow) * H_DIM + k0 + lcol);
            As[lcol][lrow] = av.x; As[lcol + 1][lrow] = av.y;
            float2 bv = *(const float2*)(B + (size_t)(n0 + lrow) * H_DIM + k0 + lcol);
            Bs[lcol][lrow] = bv.x; Bs[lcol + 1][lrow] = bv.y;
            __syncthreads();
#pragma unroll
            for (int k = 0; k < 8; k++) {
                float a[4], b[4];
#pragma unroll
                for (int q = 0; q < 4; q++) a[q] = As[k][ty * 4 + q];
#pragma unroll
                for (int q = 0; q < 4; q++) b[q] = Bs[k][tx * 4 + q];
#pragma unroll
                for (int q = 0; q < 4; q++)
#pragma unroll
                    for (int r = 0; r < 4; r++) acc[q][r] += a[q] * b[r];
            }
            __syncthreads();
        }
    }
#pragma unroll
    for (int q = 0; q < 4; q++)
#pragma unroll
        for (int r = 0; r < 4; r++)
            out[(size_t)(b0 + ty * 4 + q) * N_ENT + (n0 + tx * 4 + r)] = 0.5f * acc[q][r];
}

// ---------------------------------- launch ----------------------------------
extern "C" void kernel_launch(void* const* d_in, const int* in_sizes, int n_in,
                              void* d_out, int out_size)
{
    const float* etc_in = (const float*)d_in[0];
    const float* ett_in = (const float*)d_in[1];
    const float* mtc_in = (const float*)d_in[2];
    const float* mtt_in = (const float*)d_in[3];
    const float* eic_in = (const float*)d_in[4];
    const float* eit_in = (const float*)d_in[5];
    const float* mic_in = (const float*)d_in[6];
    const float* mit_in = (const float*)d_in[7];
    const float* W_text = (const float*)d_in[8];
    const float* b_text = (const float*)d_in[9];
    const float* W_img  = (const float*)d_in[10];
    const float* b_img  = (const float*)d_in[11];
    const float* W_gate = (const float*)d_in[12];
    const float* b_gate = (const float*)d_in[13];
    const float* ln_s   = (const float*)d_in[14];
    const float* ln_b   = (const float*)d_in[15];
    const float* W_rout = (const float*)d_in[16];
    const float* b_rout = (const float*)d_in[17];
    const float* W_exp  = (const float*)d_in[18];
    const float* b_exp  = (const float*)d_in[19];
    float* out = (float*)d_out;

    float *p_etc, *p_eic, *p_mtc, *p_mic, *p_ett, *p_eit, *p_mtt, *p_mit;
    float *p_etim, *p_mtim, *p_eitm, *p_mitm;
    float *p_ctx0, *p_ctx1, *p_ctx2, *p_ctx3;
    float *p_feti, *p_fmti, *p_feit, *p_fmit;
    float *p_wct, *p_wci, *p_bt;
    int2* p_eidx; float2* p_ew;
    cudaGetSymbolAddress((void**)&p_etc, g_etc);
    cudaGetSymbolAddress((void**)&p_eic, g_eic);
    cudaGetSymbolAddress((void**)&p_mtc, g_mtc);
    cudaGetSymbolAddress((void**)&p_mic, g_mic);
    cudaGetSymbolAddress((void**)&p_ett, g_ett);
    cudaGetSymbolAddress((void**)&p_eit, g_eit);
    cudaGetSymbolAddress((void**)&p_mtt, g_mtt);
    cudaGetSymbolAddress((void**)&p_mit, g_mit);
    cudaGetSymbolAddress((void**)&p_etim, g_eti_m);
    cudaGetSymbolAddress((void**)&p_mtim, g_mti_m);
    cudaGetSymbolAddress((void**)&p_eitm, g_eit_m);
    cudaGetSymbolAddress((void**)&p_mitm, g_mit_m);
    cudaGetSymbolAddress((void**)&p_ctx0, g_ctx0);
    cudaGetSymbolAddress((void**)&p_ctx1, g_ctx1);
    cudaGetSymbolAddress((void**)&p_ctx2, g_ctx2);
    cudaGetSymbolAddress((void**)&p_ctx3, g_ctx3);
    cudaGetSymbolAddress((void**)&p_feti, g_fe_ti);
    cudaGetSymbolAddress((void**)&p_fmti, g_fm_ti);
    cudaGetSymbolAddress((void**)&p_feit, g_fe_it);
    cudaGetSymbolAddress((void**)&p_fmit, g_fm_it);
    cudaGetSymbolAddress((void**)&p_wct, g_wc_text);
    cudaGetSymbolAddress((void**)&p_wci, g_wc_img);
    cudaGetSymbolAddress((void**)&p_bt, g_bterm);
    cudaGetSymbolAddress((void**)&p_eidx, g_eidx);
    cudaGetSymbolAddress((void**)&p_ew,   g_ew);

    // enable >48KB dynamic smem for the GEMM kernels (idempotent)
    constexpr int moe2_smem = (2 * 64 * AS_STR * 2 + 2 * 16 * BS_STR * 2) * 4;
    constexpr int moe3_smem = (2 * 96 * AS_STR * 2 + 2 * 16 * BS_STR * 2) * 4;
    cudaFuncSetAttribute(proj_tc,   cudaFuncAttributeMaxDynamicSharedMemorySize, P_SMEM_BYTES);
    cudaFuncSetAttribute(moe_tc<2>, cudaFuncAttributeMaxDynamicSharedMemorySize, moe2_smem);
    cudaFuncSetAttribute(moe_tc<3>, cudaFuncAttributeMaxDynamicSharedMemorySize, moe3_smem);

    dim3 blk(256);

    // router weight folding + exact fp32 routing from raw inputs
    combine_w_kernel<<<(D_IN * N_EXP + 255) / 256, blk>>>(W_text, W_img, W_rout, p_wct, p_wci);
    bterm_kernel<<<1, 32>>>(b_text, b_img, W_rout, b_rout, p_bt);

    router2_kernel<<<N_ENT, blk>>>(eic_in, ett_in, T_TOK, p_wci, p_wct, p_bt,
                                   p_eidx + 0 * N_ENT, p_ew + 0 * N_ENT);
    router2_kernel<<<BATCH, blk>>>(mic_in, mtt_in, T_TOK, p_wci, p_wct, p_bt,
                                   p_eidx + 1 * N_ENT, p_ew + 1 * N_ENT);
    router2_kernel<<<N_ENT, blk>>>(etc_in, eit_in, P_TOK, p_wct, p_wci, p_bt + N_EXP,
                                   p_eidx + 2 * N_ENT, p_ew + 2 * N_ENT);

    // launch #6 = the big ett projection -> gets captured by ncu (-s 5 -c 1)
    proj_tc<<<dim3(N_ENT * T_TOK / 128, 4), blk, P_SMEM_BYTES>>>(ett_in, W_text, b_text, p_ett, N_ENT * T_TOK);

    router2_kernel<<<BATCH, blk>>>(mtc_in, mit_in, P_TOK, p_wct, p_wci, p_bt + N_EXP,
                                   p_eidx + 3 * N_ENT, p_ew + 3 * N_ENT);

    // remaining projections (3xTF32 tensor cores)
    proj_tc<<<dim3(N_ENT / 128, 4), blk, P_SMEM_BYTES>>>(etc_in, W_text, b_text, p_etc, N_ENT);
    proj_tc<<<dim3(BATCH / 128, 4), blk, P_SMEM_BYTES>>>(mtc_in, W_text, b_text, p_mtc, BATCH);
    proj_tc<<<dim3(BATCH * T_TOK / 128, 4), blk, P_SMEM_BYTES>>>(mtt_in, W_text, b_text, p_mtt, BATCH * T_TOK);
    proj_tc<<<dim3(N_ENT / 128, 4), blk, P_SMEM_BYTES>>>(eic_in, W_img, b_img, p_eic, N_ENT);
    proj_tc<<<dim3(N_ENT * P_TOK / 128, 4), blk, P_SMEM_BYTES>>>(eit_in, W_img, b_img, p_eit, N_ENT * P_TOK);
    proj_tc<<<dim3(BATCH / 128, 4), blk, P_SMEM_BYTES>>>(mic_in, W_img, b_img, p_mic, BATCH);
    proj_tc<<<dim3(BATCH * P_TOK / 128, 4), blk, P_SMEM_BYTES>>>(mit_in, W_img, b_img, p_mit, BATCH * P_TOK);

    // MoE GEMMs (combined expert pair, 3xTF32)
    moe_tc<2><<<dim3(4, 1, N_ENT), blk, moe2_smem>>>(p_etc, p_eit, 50, W_exp, b_exp,
                                          p_eidx + 0 * N_ENT, p_ew + 0 * N_ENT, p_etim);
    moe_tc<2><<<dim3(4, 1, BATCH), blk, moe2_smem>>>(p_mtc, p_mit, 50, W_exp, b_exp,
                                          p_eidx + 1 * N_ENT, p_ew + 1 * N_ENT, p_mtim);
    moe_tc<3><<<dim3(4, 1, N_ENT), blk, moe3_smem>>>(p_eic, p_ett, 65, W_exp, b_exp,
                                          p_eidx + 2 * N_ENT, p_ew + 2 * N_ENT, p_eitm);
    moe_tc<3><<<dim3(4, 1, BATCH), blk, moe3_smem>>>(p_mic, p_mtt, 65, W_exp, b_exp,
                                          p_eidx + 3 * N_ENT, p_ew + 3 * N_ENT, p_mitm);

    // cross attention
    cross_kernel<<<N_ENT, blk>>>(p_etim, 50, p_ctx0);
    cross_kernel<<<BATCH, blk>>>(p_mtim, 50, p_ctx1);
    cross_kernel<<<N_ENT, blk>>>(p_eitm, 65, p_ctx2);
    cross_kernel<<<BATCH, blk>>>(p_mitm, 65, p_ctx3);

    // gate + residual + LN
    gate_ln_kernel<<<N_ENT, blk>>>(p_etc, p_ctx0, W_gate, b_gate, ln_s, ln_b, p_feti, 1);
    gate_ln_kernel<<<BATCH, blk>>>(p_mtc, p_ctx1, W_gate, b_gate, ln_s, ln_b, p_fmti, 0);
    gate_ln_kernel<<<N_ENT, blk>>>(p_eic, p_ctx2, W_gate, b_gate, ln_s, ln_b, p_feit, 1);
    gate_ln_kernel<<<BATCH, blk>>>(p_mic, p_ctx3, W_gate, b_gate, ln_s, ln_b, p_fmit, 0);

    // final score
    score_kernel<<<dim3(N_ENT / 64, BATCH / 64), blk>>>(p_fmti, p_feti, p_fmit, p_feit, out);
}

// round 7
// speedup vs baseline: 1.0793x; 1.0793x over previous
#include <cuda_runtime.h>
#include <math.h>
#include <stdint.h>

#define N_ENT 1024
#define BATCH 128
#define T_TOK 64
#define P_TOK 49
#define D_IN 768
#define H_DIM 512
#define N_EXP 8

// ----------------------------- static scratch ------------------------------
__device__ float g_etc[N_ENT * H_DIM];
__device__ float g_eic[N_ENT * H_DIM];
__device__ float g_mtc[BATCH * H_DIM];
__device__ float g_mic[BATCH * H_DIM];
__device__ float g_ett[N_ENT * T_TOK * H_DIM];
__device__ float g_eit[N_ENT * P_TOK * H_DIM];
__device__ float g_mtt[BATCH * T_TOK * H_DIM];
__device__ float g_mit[BATCH * P_TOK * H_DIM];

__device__ float g_eti_m[N_ENT * 50 * H_DIM];
__device__ float g_mti_m[BATCH * 50 * H_DIM];
__device__ float g_eit_m[N_ENT * 65 * H_DIM];
__device__ float g_mit_m[BATCH * 65 * H_DIM];

__device__ int2   g_eidx[4][N_ENT];
__device__ float2 g_ew[4][N_ENT];

__device__ float g_ctx0[N_ENT * H_DIM];
__device__ float g_ctx1[BATCH * H_DIM];
__device__ float g_ctx2[N_ENT * H_DIM];
__device__ float g_ctx3[BATCH * H_DIM];

__device__ float g_fe_ti[N_ENT * H_DIM];
__device__ float g_fm_ti[BATCH * H_DIM];
__device__ float g_fe_it[N_ENT * H_DIM];
__device__ float g_fm_it[BATCH * H_DIM];

__device__ float g_wc_text[D_IN * N_EXP];
__device__ float g_wc_img[D_IN * N_EXP];
__device__ float g_bterm[2 * N_EXP];

// ------------------------------ tf32 helpers -------------------------------
__device__ __forceinline__ void split_tf32(float x, uint32_t& hi, uint32_t& lo)
{
    asm("cvt.rna.tf32.f32 %0, %1;" : "=r"(hi) : "f"(x));
    float r = x - __uint_as_float(hi);
    asm("cvt.rna.tf32.f32 %0, %1;" : "=r"(lo) : "f"(r));
}

__device__ __forceinline__ void mma8(float* c, const uint32_t* a, const uint32_t* b)
{
    asm volatile(
        "mma.sync.aligned.m16n8k8.row.col.f32.tf32.tf32.f32 "
        "{%0,%1,%2,%3}, {%4,%5,%6,%7}, {%8,%9}, {%0,%1,%2,%3};"
        : "+f"(c[0]), "+f"(c[1]), "+f"(c[2]), "+f"(c[3])
        : "r"(a[0]), "r"(a[1]), "r"(a[2]), "r"(a[3]), "r"(b[0]), "r"(b[1]));
}

#define AS_STR 20
#define BS_STR 136   // 136 mod 32 == 8 -> conflict-free B fragment loads

// ----------------- proj (3xTF32): C[M,512]=A[M,768]@W+bias -----------------
__global__ __launch_bounds__(256) void proj_tc(
    const float* __restrict__ A, const float* __restrict__ W,
    const float* __restrict__ bias, float* __restrict__ C, int M)
{
    __shared__ uint32_t AsH[128 * AS_STR], AsL[128 * AS_STR];
    __shared__ uint32_t BsH[16 * BS_STR], BsL[16 * BS_STR];

    const int tid = threadIdx.x;
    const int row0 = blockIdx.x * 128;
    const int col0 = blockIdx.y * 128;
    const int warp = tid >> 5, lane = tid & 31;
    const int wm = warp >> 2, wn = warp & 3;
    const int gid = lane >> 2, tig = lane & 3;

    const int ar  = tid >> 2;
    const int ac4 = (tid & 3) * 4;
    const int bk  = tid >> 5;
    const int bc4 = (tid & 31) * 4;

    float acc[4][4][4];
#pragma unroll
    for (int a = 0; a < 4; a++)
#pragma unroll
        for (int b = 0; b < 4; b++)
#pragma unroll
            for (int c = 0; c < 4; c++) acc[a][b][c] = 0.f;

    float4 pa[2], pb[2];
    const float* Abase = A + (size_t)row0 * D_IN;

    auto load_tiles = [&](int k0) {
        pa[0] = *(const float4*)(Abase + (size_t)ar * D_IN + k0 + ac4);
        pa[1] = *(const float4*)(Abase + (size_t)(ar + 64) * D_IN + k0 + ac4);
        pb[0] = *(const float4*)(W + (size_t)(k0 + bk) * H_DIM + col0 + bc4);
        pb[1] = *(const float4*)(W + (size_t)(k0 + bk + 8) * H_DIM + col0 + bc4);
    };
    auto store_tiles = [&]() {
#pragma unroll
        for (int p = 0; p < 2; p++) {
            float v[4] = {pa[p].x, pa[p].y, pa[p].z, pa[p].w};
            uint4 h, l;
            split_tf32(v[0], h.x, l.x); split_tf32(v[1], h.y, l.y);
            split_tf32(v[2], h.z, l.z); split_tf32(v[3], h.w, l.w);
            int base = (ar + p * 64) * AS_STR + ac4;
            *(uint4*)&AsH[base] = h; *(uint4*)&AsL[base] = l;

            float u[4] = {pb[p].x, pb[p].y, pb[p].z, pb[p].w};
            split_tf32(u[0], h.x, l.x); split_tf32(u[1], h.y, l.y);
            split_tf32(u[2], h.z, l.z); split_tf32(u[3], h.w, l.w);
            int bbase = (bk + p * 8) * BS_STR + bc4;
            *(uint4*)&BsH[bbase] = h; *(uint4*)&BsL[bbase] = l;
        }
    };

    load_tiles(0);
    store_tiles();
    __syncthreads();

    const int NKB = D_IN / 16;
    for (int kb = 0; kb < NKB; kb++) {
        if (kb + 1 < NKB) load_tiles((kb + 1) * 16);
#pragma unroll
        for (int kk = 0; kk < 16; kk += 8) {
            uint32_t ah[4][4], al[4][4], bh[4][2], bl[4][2];
#pragma unroll
            for (int mt = 0; mt < 4; mt++) {
                int b0 = (wm * 64 + mt * 16 + gid) * AS_STR + kk + tig;
                ah[mt][0] = AsH[b0];     ah[mt][1] = AsH[b0 + 8 * AS_STR];
                ah[mt][2] = AsH[b0 + 4]; ah[mt][3] = AsH[b0 + 8 * AS_STR + 4];
                al[mt][0] = AsL[b0];     al[mt][1] = AsL[b0 + 8 * AS_STR];
                al[mt][2] = AsL[b0 + 4]; al[mt][3] = AsL[b0 + 8 * AS_STR + 4];
            }
#pragma unroll
            for (int nt = 0; nt < 4; nt++) {
                int b0 = (kk + tig) * BS_STR + wn * 32 + nt * 8 + gid;
                bh[nt][0] = BsH[b0]; bh[nt][1] = BsH[b0 + 4 * BS_STR];
                bl[nt][0] = BsL[b0]; bl[nt][1] = BsL[b0 + 4 * BS_STR];
            }
#pragma unroll
            for (int mt = 0; mt < 4; mt++)
#pragma unroll
                for (int nt = 0; nt < 4; nt++) mma8(acc[mt][nt], ah[mt], bh[nt]);
#pragma unroll
            for (int mt = 0; mt < 4; mt++)
#pragma unroll
                for (int nt = 0; nt < 4; nt++) mma8(acc[mt][nt], ah[mt], bl[nt]);
#pragma unroll
            for (int mt = 0; mt < 4; mt++)
#pragma unroll
                for (int nt = 0; nt < 4; nt++) mma8(acc[mt][nt], al[mt], bh[nt]);
        }
        __syncthreads();
        if (kb + 1 < NKB) { store_tiles(); __syncthreads(); }
    }

#pragma unroll
    for (int mt = 0; mt < 4; mt++) {
        int m = row0 + wm * 64 + mt * 16 + gid;
#pragma unroll
        for (int nt = 0; nt < 4; nt++) {
            int n = col0 + wn * 32 + nt * 8 + tig * 2;
            float2 bv = *(const float2*)(bias + n);
            *(float2*)(C + (size_t)m * H_DIM + n) =
                make_float2(acc[mt][nt][0] + bv.x, acc[mt][nt][1] + bv.y);
            *(float2*)(C + (size_t)(m + 8) * H_DIM + n) =
                make_float2(acc[mt][nt][2] + bv.x, acc[mt][nt][3] + bv.y);
        }
    }
}

// ------- MoE (3xTF32): out = x @ (w0*We[e0]+w1*We[e1]) + combined bias ------
template<int WM>
__global__ __launch_bounds__(256) void moe_tc(
    const float* __restrict__ cls, const float* __restrict__ tok, int S,
    const float* __restrict__ We, const float* __restrict__ be,
    const int2* __restrict__ eidx, const float2* __restrict__ ew,
    float* __restrict__ out)
{
    constexpr int BM = WM * 32;
    constexpr int PF = (BM * 4 + 255) / 256;
    __shared__ uint32_t AsH[BM * AS_STR], AsL[BM * AS_STR];
    __shared__ uint32_t BsH[16 * BS_STR], BsL[16 * BS_STR];

    const int i = blockIdx.z;
    const int col0 = blockIdx.x * 128;
    const int2 e = eidx[i];
    const float2 w = ew[i];
    const float* W0 = We + (size_t)e.x * H_DIM * H_DIM;
    const float* W1 = We + (size_t)e.y * H_DIM * H_DIM;

    const int tid = threadIdx.x;
    const int warp = tid >> 5, lane = tid & 31;
    const int wm = warp >> 2, wn = warp & 3;
    const int gid = lane >> 2, tig = lane & 3;
    const int bk = tid >> 5, bc4 = (tid & 31) * 4;

    float acc[WM][4][4];
#pragma unroll
    for (int a = 0; a < WM; a++)
#pragma unroll
        for (int b = 0; b < 4; b++)
#pragma unroll
            for (int c = 0; c < 4; c++) acc[a][b][c] = 0.f;

    float4 pa[PF], pb[2];

    auto load_tiles = [&](int k0) {
#pragma unroll
        for (int p = 0; p < PF; p++) {
            int idx = p * 256 + tid;
            float4 v = make_float4(0.f, 0.f, 0.f, 0.f);
            if (idx < BM * 4) {
                int t = idx >> 2;
                if (t < S) {
                    const float* rp = (t == 0)
                        ? (cls + (size_t)i * H_DIM)
                        : (tok + ((size_t)i * (S - 1) + (t - 1)) * H_DIM);
                    v = *(const float4*)(rp + k0 + (idx & 3) * 4);
                }
            }
            pa[p] = v;
        }
#pragma unroll
        for (int p = 0; p < 2; p++) {
            size_t off = (size_t)(k0 + bk + p * 8) * H_DIM + col0 + bc4;
            float4 v0 = *(const float4*)(W0 + off);
            float4 v1 = *(const float4*)(W1 + off);
            pb[p] = make_float4(w.x * v0.x + w.y * v1.x, w.x * v0.y + w.y * v1.y,
                                w.x * v0.z + w.y * v1.z, w.x * v0.w + w.y * v1.w);
        }
    };
    auto store_tiles = [&]() {
#pragma unroll
        for (int p = 0; p < PF; p++) {
            int idx = p * 256 + tid;
            if (idx < BM * 4) {
                float v[4] = {pa[p].x, pa[p].y, pa[p].z, pa[p].w};
                uint4 h, l;
                split_tf32(v[0], h.x, l.x); split_tf32(v[1], h.y, l.y);
                split_tf32(v[2], h.z, l.z); split_tf32(v[3], h.w, l.w);
                int base = (idx >> 2) * AS_STR + (idx & 3) * 4;
                *(uint4*)&AsH[base] = h; *(uint4*)&AsL[base] = l;
            }
        }
#pragma unroll
        for (int p = 0; p < 2; p++) {
            float u[4] = {pb[p].x, pb[p].y, pb[p].z, pb[p].w};
            uint4 h, l;
            split_tf32(u[0], h.x, l.x); split_tf32(u[1], h.y, l.y);
            split_tf32(u[2], h.z, l.z); split_tf32(u[3], h.w, l.w);
            int bbase = (bk + p * 8) * BS_STR + bc4;
            *(uint4*)&BsH[bbase] = h; *(uint4*)&BsL[bbase] = l;
        }
    };

    load_tiles(0);
    store_tiles();
    __syncthreads();

    const int NKB = H_DIM / 16;
    for (int kb = 0; kb < NKB; kb++) {
        if (kb + 1 < NKB) load_tiles((kb + 1) * 16);
#pragma unroll
        for (int kk = 0; kk < 16; kk += 8) {
            uint32_t ah[WM][4], al[WM][4], bh[4][2], bl[4][2];
#pragma unroll
            for (int mt = 0; mt < WM; mt++) {
                int b0 = (wm * WM * 16 + mt * 16 + gid) * AS_STR + kk + tig;
                ah[mt][0] = AsH[b0];     ah[mt][1] = AsH[b0 + 8 * AS_STR];
                ah[mt][2] = AsH[b0 + 4]; ah[mt][3] = AsH[b0 + 8 * AS_STR + 4];
                al[mt][0] = AsL[b0];     al[mt][1] = AsL[b0 + 8 * AS_STR];
                al[mt][2] = AsL[b0 + 4]; al[mt][3] = AsL[b0 + 8 * AS_STR + 4];
            }
#pragma unroll
            for (int nt = 0; nt < 4; nt++) {
                int b0 = (kk + tig) * BS_STR + wn * 32 + nt * 8 + gid;
                bh[nt][0] = BsH[b0]; bh[nt][1] = BsH[b0 + 4 * BS_STR];
                bl[nt][0] = BsL[b0]; bl[nt][1] = BsL[b0 + 4 * BS_STR];
            }
#pragma unroll
            for (int mt = 0; mt < WM; mt++)
#pragma unroll
                for (int nt = 0; nt < 4; nt++) mma8(acc[mt][nt], ah[mt], bh[nt]);
#pragma unroll
            for (int mt = 0; mt < WM; mt++)
#pragma unroll
                for (int nt = 0; nt < 4; nt++) mma8(acc[mt][nt], ah[mt], bl[nt]);
#pragma unroll
            for (int mt = 0; mt < WM; mt++)
#pragma unroll
                for (int nt = 0; nt < 4; nt++) mma8(acc[mt][nt], al[mt], bh[nt]);
        }
        __syncthreads();
        if (kb + 1 < NKB) { store_tiles(); __syncthreads(); }
    }

#pragma unroll
    for (int mt = 0; mt < WM; mt++) {
        int t = wm * WM * 16 + mt * 16 + gid;
#pragma unroll
        for (int nt = 0; nt < 4; nt++) {
            int n = col0 + wn * 32 + nt * 8 + tig * 2;
            float b0 = w.x * be[e.x * H_DIM + n]     + w.y * be[e.y * H_DIM + n];
            float b1 = w.x * be[e.x * H_DIM + n + 1] + w.y * be[e.y * H_DIM + n + 1];
            if (t < S)
                *(float2*)(out + ((size_t)i * S + t) * H_DIM + n) =
                    make_float2(acc[mt][nt][0] + b0, acc[mt][nt][1] + b1);
            if (t + 8 < S)
                *(float2*)(out + ((size_t)i * S + t + 8) * H_DIM + n) =
                    make_float2(acc[mt][nt][2] + b0, acc[mt][nt][3] + b1);
        }
    }
}

// --------------------- router weight folding (fp32-exact) ------------------
__global__ void combine_w_kernel(const float* __restrict__ Wt, const float* __restrict__ Wi,
                                 const float* __restrict__ Wr,
                                 float* __restrict__ WcT, float* __restrict__ WcI)
{
    int idx = blockIdx.x * blockDim.x + threadIdx.x;
    if (idx >= D_IN * N_EXP) return;
    int k = idx >> 3, e = idx & 7;
    float st = 0.f, si = 0.f;
    for (int h = 0; h < H_DIM; h++) {
        float wr = Wr[h * N_EXP + e];
        st += Wt[(size_t)k * H_DIM + h] * wr;
        si += Wi[(size_t)k * H_DIM + h] * wr;
    }
    WcT[idx] = st;
    WcI[idx] = si;
}

__global__ void bterm_kernel(const float* __restrict__ bt, const float* __restrict__ bi,
                             const float* __restrict__ Wr, const float* __restrict__ br,
                             float* __restrict__ bterm)
{
    int e = threadIdx.x;
    if (e < N_EXP) {
        float sA = 0.f, sB = 0.f;
        for (int h = 0; h < H_DIM; h++) {
            float wr = Wr[h * N_EXP + e];
            sA += (bi[h] + 64.f * bt[h]) * wr;   // y = [img cls, 64 text tokens]
            sB += (bt[h] + 49.f * bi[h]) * wr;   // y = [text cls, 49 img tokens]
        }
        bterm[e]         = sA / 65.f + br[e];
        bterm[N_EXP + e] = sB / 50.f + br[e];
    }
}

// -------- router: stage1 bandwidth token-sum (float4), stage2 logits -------
__global__ __launch_bounds__(256) void router2_kernel(
    const float* __restrict__ cls, const float* __restrict__ tok, int Sm1,
    const float* __restrict__ WcCls, const float* __restrict__ WcTok,
    const float* __restrict__ bt,
    int2* __restrict__ eidx, float2* __restrict__ ew)
{
    const int i = blockIdx.x, tid = threadIdx.x;
    __shared__ float sumtok[D_IN];
    __shared__ float red[8][N_EXP];
    __shared__ float logits[N_EXP];

    // stage 1: sum of Sm1 token rows, float4, 4 independent chains
    if (tid < 192) {
        const float4* tp = (const float4*)(tok + (size_t)i * Sm1 * D_IN) + tid;
        float4 s0 = make_float4(0.f, 0.f, 0.f, 0.f), s1 = s0, s2 = s0, s3 = s0;
        int t = 0;
        for (; t + 4 <= Sm1; t += 4) {
            float4 a = tp[(size_t)(t + 0) * 192];
            float4 b = tp[(size_t)(t + 1) * 192];
            float4 c = tp[(size_t)(t + 2) * 192];
            float4 d = tp[(size_t)(t + 3) * 192];
            s0.x += a.x; s0.y += a.y; s0.z += a.z; s0.w += a.w;
            s1.x += b.x; s1.y += b.y; s1.z += b.z; s1.w += b.w;
            s2.x += c.x; s2.y += c.y; s2.z += c.z; s2.w += c.w;
            s3.x += d.x; s3.y += d.y; s3.z += d.z; s3.w += d.w;
        }
        for (; t < Sm1; t++) {
            float4 a = tp[(size_t)t * 192];
            s0.x += a.x; s0.y += a.y; s0.z += a.z; s0.w += a.w;
        }
        float4 s = make_float4(s0.x + s1.x + s2.x + s3.x, s0.y + s1.y + s2.y + s3.y,
                               s0.z + s1.z + s2.z + s3.z, s0.w + s1.w + s2.w + s3.w);
        *(float4*)&sumtok[tid * 4] = s;
    }
    __syncthreads();

    // stage 2: logits (cls dot WcCls + sumtok dot WcTok per expert)
    const int warp = tid >> 5, lane = tid & 31;
    {
        float part[N_EXP];
#pragma unroll
        for (int e = 0; e < N_EXP; e++) part[e] = 0.f;
        for (int c = tid; c < D_IN; c += 256) {
            float cl = cls[(size_t)i * D_IN + c];
            float s = sumtok[c];
#pragma unroll
            for (int e = 0; e < N_EXP; e++)
                part[e] += cl * WcCls[c * N_EXP + e] + s * WcTok[c * N_EXP + e];
        }
#pragma unroll
        for (int o = 16; o; o >>= 1)
#pragma unroll
            for (int e = 0; e < N_EXP; e++)
                part[e] += __shfl_down_sync(0xffffffffu, part[e], o);
        if (lane == 0)
#pragma unroll
            for (int e = 0; e < N_EXP; e++) red[warp][e] = part[e];
    }
    __syncthreads();
    if (tid < N_EXP) {
        float l = 0.f;
        for (int wq = 0; wq < 8; wq++) l += red[wq][tid];
        logits[tid] = l / (float)(Sm1 + 1) + bt[tid];
    }
    __syncthreads();
    if (tid == 0) {
        int b0 = 0;
        for (int e = 1; e < N_EXP; e++)
            if (logits[e] > logits[b0]) b0 = e;
        int b1 = (b0 == 0) ? 1 : 0;
        for (int e = 0; e < N_EXP; e++)
            if (e != b0 && logits[e] > logits[b1]) b1 = e;
        float e1v = expf(logits[b1] - logits[b0]);
        float inv = 1.0f / (1.0f + e1v);
        eidx[i] = make_int2(b0, b1);
        ew[i] = make_float2(inv, e1v * inv);
    }
}

// ---------------------- cross attention (vectorized) -----------------------
__global__ __launch_bounds__(256) void cross_kernel(
    const float* __restrict__ moe_out, int S, float* __restrict__ ctx)
{
    const int i = blockIdx.x;
    __shared__ float4 cls4[H_DIM / 4];
    __shared__ float prob[64];
    const int tid = threadIdx.x;
    const float* base = moe_out + (size_t)i * S * H_DIM;

    if (tid < H_DIM / 4) cls4[tid] = ((const float4*)base)[tid];
    __syncthreads();

    const int nt = S - 1;
    const int warp = tid >> 5, lane = tid & 31;
    for (int s = warp; s < nt; s += 8) {
        const float4* tr = (const float4*)(base + (size_t)(s + 1) * H_DIM);
        float p = 0.f;
#pragma unroll
        for (int q = 0; q < 4; q++) {
            float4 a = cls4[lane + 32 * q];
            float4 b = tr[lane + 32 * q];
            p += a.x * b.x + a.y * b.y + a.z * b.z + a.w * b.w;
        }
#pragma unroll
        for (int o = 16; o; o >>= 1) p += __shfl_down_sync(0xffffffffu, p, o);
        if (lane == 0) prob[s] = p;
    }
    __syncthreads();

    if (tid == 0) {
        float mx = -1e30f;
        for (int s = 0; s < nt; s++) mx = fmaxf(mx, prob[s]);
        float sum = 0.f;
        for (int s = 0; s < nt; s++) { float e = expf(prob[s] - mx); prob[s] = e; sum += e; }
        float inv = 1.0f / sum;
        for (int s = 0; s < nt; s++) prob[s] *= inv;
    }
    __syncthreads();

    // weighted sum: 256 threads x float2 = 512 cols
    float2 acc = make_float2(0.f, 0.f);
    const float2* b2 = (const float2*)(base + H_DIM) + tid;   // token rows start at t=1
#pragma unroll 4
    for (int s = 0; s < nt; s++) {
        float2 v = b2[(size_t)s * (H_DIM / 2)];
        float pw = prob[s];
        acc.x += pw * v.x; acc.y += pw * v.y;
    }
    ((float2*)(ctx + (size_t)i * H_DIM))[tid] = acc;
}

// --------------------------- gate + residual + LN ---------------------------
__global__ __launch_bounds__(256) void gate_ln_kernel(
    const float* __restrict__ ori, const float* __restrict__ ctx,
    const float* __restrict__ Wg, const float* __restrict__ bg,
    const float* __restrict__ ls, const float* __restrict__ lb,
    float* __restrict__ out, int gate_from_ctx)
{
    const int i = blockIdx.x;
    __shared__ float v[H_DIM];
    __shared__ float red[256];
    const int tid = threadIdx.x;
    const float* orow = ori + (size_t)i * H_DIM;
    const float* crow = ctx + (size_t)i * H_DIM;

    float p = 0.f;
    for (int c = tid; c < H_DIM; c += 256) {
        float gs = gate_from_ctx ? crow[c] : orow[c];
        p += gs * Wg[c];
    }
    red[tid] = p; __syncthreads();
    for (int o = 128; o; o >>= 1) { if (tid < o) red[tid] += red[tid + o]; __syncthreads(); }
    float gate = tanhf(red[0] + bg[0]);
    __syncthreads();

    float sum = 0.f;
    for (int c = tid; c < H_DIM; c += 256) {
        float val = orow[c] * gate + crow[c];
        v[c] = val; sum += val;
    }
    red[tid] = sum; __syncthreads();
    for (int o = 128; o; o >>= 1) { if (tid < o) red[tid] += red[tid + o]; __syncthreads(); }
    float mean = red[0] / (float)H_DIM;
    __syncthreads();

    float var = 0.f;
    for (int c = tid; c < H_DIM; c += 256) { float d = v[c] - mean; var += d * d; }
    red[tid] = var; __syncthreads();
    for (int o = 128; o; o >>= 1) { if (tid < o) red[tid] += red[tid + o]; __syncthreads(); }
    float rstd = rsqrtf(red[0] / (float)H_DIM + 1e-5f);

    for (int c = tid; c < H_DIM; c += 256)
        out[(size_t)i * H_DIM + c] = (v[c] - mean) * rstd * ls[c] + lb[c];
}

// -------------------------------- final score -------------------------------
__global__ __launch_bounds__(256) void score_kernel(
    const float* __restrict__ mti, const float* __restrict__ eti,
    const float* __restrict__ mit, const float* __restrict__ eit,
    float* __restrict__ out)
{
    __shared__ float As[8][64];
    __shared__ float Bs[8][64];
    const int n0 = blockIdx.x * 64;
    const int b0 = blockIdx.y * 64;
    const int tid = threadIdx.x;
    const int tx = tid & 15, ty = tid >> 4;
    const int lrow = tid >> 2, lcol = (tid & 3) * 2;

    float acc[4][4];
#pragma unroll
    for (int q = 0; q < 4; q++)
#pragma unroll
        for (int r = 0; r < 4; r++) acc[q][r] = 0.f;

#pragma unroll
    for (int pass = 0; pass < 2; pass++) {
        const float* A = pass ? mit : mti;
        const float* B = pass ? eit : eti;
        for (int k0 = 0; k0 < H_DIM; k0 += 8) {
            float2 av = *(const float2*)(A + (size_t)(b0 + lrow) * H_DIM + k0 + lcol);
            As[lcol][lrow] = av.x; As[lcol + 1][lrow] = av.y;
            float2 bv = *(const float2*)(B + (size_t)(n0 + lrow) * H_DIM + k0 + lcol);
            Bs[lcol][lrow] = bv.x; Bs[lcol + 1][lrow] = bv.y;
            __syncthreads();
#pragma unroll
            for (int k = 0; k < 8; k++) {
                float a[4], b[4];
#pragma unroll
                for (int q = 0; q < 4; q++) a[q] = As[k][ty * 4 + q];
#pragma unroll
                for (int q = 0; q < 4; q++) b[q] = Bs[k][tx * 4 + q];
#pragma unroll
                for (int q = 0; q < 4; q++)
#pragma unroll
                    for (int r = 0; r < 4; r++) acc[q][r] += a[q] * b[r];
            }
            __syncthreads();
        }
    }
#pragma unroll
    for (int q = 0; q < 4; q++)
#pragma unroll
        for (int r = 0; r < 4; r++)
            out[(size_t)(b0 + ty * 4 + q) * N_ENT + (n0 + tx * 4 + r)] = 0.5f * acc[q][r];
}

// ---------------------------------- launch ----------------------------------
extern "C" void kernel_launch(void* const* d_in, const int* in_sizes, int n_in,
                              void* d_out, int out_size)
{
    const float* etc_in = (const float*)d_in[0];
    const float* ett_in = (const float*)d_in[1];
    const float* mtc_in = (const float*)d_in[2];
    const float* mtt_in = (const float*)d_in[3];
    const float* eic_in = (const float*)d_in[4];
    const float* eit_in = (const float*)d_in[5];
    const float* mic_in = (const float*)d_in[6];
    const float* mit_in = (const float*)d_in[7];
    const float* W_text = (const float*)d_in[8];
    const float* b_text = (const float*)d_in[9];
    const float* W_img  = (const float*)d_in[10];
    const float* b_img  = (const float*)d_in[11];
    const float* W_gate = (const float*)d_in[12];
    const float* b_gate = (const float*)d_in[13];
    const float* ln_s   = (const float*)d_in[14];
    const float* ln_b   = (const float*)d_in[15];
    const float* W_rout = (const float*)d_in[16];
    const float* b_rout = (const float*)d_in[17];
    const float* W_exp  = (const float*)d_in[18];
    const float* b_exp  = (const float*)d_in[19];
    float* out = (float*)d_out;

    float *p_etc, *p_eic, *p_mtc, *p_mic, *p_ett, *p_eit, *p_mtt, *p_mit;
    float *p_etim, *p_mtim, *p_eitm, *p_mitm;
    float *p_ctx0, *p_ctx1, *p_ctx2, *p_ctx3;
    float *p_feti, *p_fmti, *p_feit, *p_fmit;
    float *p_wct, *p_wci, *p_bt;
    int2* p_eidx; float2* p_ew;
    cudaGetSymbolAddress((void**)&p_etc, g_etc);
    cudaGetSymbolAddress((void**)&p_eic, g_eic);
    cudaGetSymbolAddress((void**)&p_mtc, g_mtc);
    cudaGetSymbolAddress((void**)&p_mic, g_mic);
    cudaGetSymbolAddress((void**)&p_ett, g_ett);
    cudaGetSymbolAddress((void**)&p_eit, g_eit);
    cudaGetSymbolAddress((void**)&p_mtt, g_mtt);
    cudaGetSymbolAddress((void**)&p_mit, g_mit);
    cudaGetSymbolAddress((void**)&p_etim, g_eti_m);
    cudaGetSymbolAddress((void**)&p_mtim, g_mti_m);
    cudaGetSymbolAddress((void**)&p_eitm, g_eit_m);
    cudaGetSymbolAddress((void**)&p_mitm, g_mit_m);
    cudaGetSymbolAddress((void**)&p_ctx0, g_ctx0);
    cudaGetSymbolAddress((void**)&p_ctx1, g_ctx1);
    cudaGetSymbolAddress((void**)&p_ctx2, g_ctx2);
    cudaGetSymbolAddress((void**)&p_ctx3, g_ctx3);
    cudaGetSymbolAddress((void**)&p_feti, g_fe_ti);
    cudaGetSymbolAddress((void**)&p_fmti, g_fm_ti);
    cudaGetSymbolAddress((void**)&p_feit, g_fe_it);
    cudaGetSymbolAddress((void**)&p_fmit, g_fm_it);
    cudaGetSymbolAddress((void**)&p_wct, g_wc_text);
    cudaGetSymbolAddress((void**)&p_wci, g_wc_img);
    cudaGetSymbolAddress((void**)&p_bt, g_bterm);
    cudaGetSymbolAddress((void**)&p_eidx, g_eidx);
    cudaGetSymbolAddress((void**)&p_ew,   g_ew);

    dim3 blk(256);

    // 1-2: router weight folding
    combine_w_kernel<<<(D_IN * N_EXP + 255) / 256, blk>>>(W_text, W_img, W_rout, p_wct, p_wci);
    bterm_kernel<<<1, 32>>>(b_text, b_img, W_rout, b_rout, p_bt);

    // 3: first big router
    router2_kernel<<<N_ENT, blk>>>(eic_in, ett_in, T_TOK, p_wci, p_wct, p_bt,
                                   p_eidx + 0 * N_ENT, p_ew + 0 * N_ENT);

    // 4: big ett projection — positioned for ncu capture (-s 5 + 2 harness launches)
    proj_tc<<<dim3(N_ENT * T_TOK / 128, 4), blk>>>(ett_in, W_text, b_text, p_ett, N_ENT * T_TOK);

    // remaining routers
    router2_kernel<<<BATCH, blk>>>(mic_in, mtt_in, T_TOK, p_wci, p_wct, p_bt,
                                   p_eidx + 1 * N_ENT, p_ew + 1 * N_ENT);
    router2_kernel<<<N_ENT, blk>>>(etc_in, eit_in, P_TOK, p_wct, p_wci, p_bt + N_EXP,
                                   p_eidx + 2 * N_ENT, p_ew + 2 * N_ENT);
    router2_kernel<<<BATCH, blk>>>(mtc_in, mit_in, P_TOK, p_wct, p_wci, p_bt + N_EXP,
                                   p_eidx + 3 * N_ENT, p_ew + 3 * N_ENT);

    // remaining projections
    proj_tc<<<dim3(N_ENT / 128, 4), blk>>>(etc_in, W_text, b_text, p_etc, N_ENT);
    proj_tc<<<dim3(BATCH / 128, 4), blk>>>(mtc_in, W_text, b_text, p_mtc, BATCH);
    proj_tc<<<dim3(BATCH * T_TOK / 128, 4), blk>>>(mtt_in, W_text, b_text, p_mtt, BATCH * T_TOK);
    proj_tc<<<dim3(N_ENT / 128, 4), blk>>>(eic_in, W_img, b_img, p_eic, N_ENT);
    proj_tc<<<dim3(N_ENT * P_TOK / 128, 4), blk>>>(eit_in, W_img, b_img, p_eit, N_ENT * P_TOK);
    proj_tc<<<dim3(BATCH / 128, 4), blk>>>(mic_in, W_img, b_img, p_mic, BATCH);
    proj_tc<<<dim3(BATCH * P_TOK / 128, 4), blk>>>(mit_in, W_img, b_img, p_mit, BATCH * P_TOK);

    // MoE GEMMs (combined expert pair, 3xTF32)
    moe_tc<2><<<dim3(4, 1, N_ENT), blk>>>(p_etc, p_eit, 50, W_exp, b_exp,
                                          p_eidx + 0 * N_ENT, p_ew + 0 * N_ENT, p_etim);
    moe_tc<2><<<dim3(4, 1, BATCH), blk>>>(p_mtc, p_mit, 50, W_exp, b_exp,
                                          p_eidx + 1 * N_ENT, p_ew + 1 * N_ENT, p_mtim);
    moe_tc<3><<<dim3(4, 1, N_ENT), blk>>>(p_eic, p_ett, 65, W_exp, b_exp,
                                          p_eidx + 2 * N_ENT, p_ew + 2 * N_ENT, p_eitm);
    moe_tc<3><<<dim3(4, 1, BATCH), blk>>>(p_mic, p_mtt, 65, W_exp, b_exp,
                                          p_eidx + 3 * N_ENT, p_ew + 3 * N_ENT, p_mitm);

    // cross attention
    cross_kernel<<<N_ENT, blk>>>(p_etim, 50, p_ctx0);
    cross_kernel<<<BATCH, blk>>>(p_mtim, 50, p_ctx1);
    cross_kernel<<<N_ENT, blk>>>(p_eitm, 65, p_ctx2);
    cross_kernel<<<BATCH, blk>>>(p_mitm, 65, p_ctx3);

    // gate + residual + LN
    gate_ln_kernel<<<N_ENT, blk>>>(p_etc, p_ctx0, W_gate, b_gate, ln_s, ln_b, p_feti, 1);
    gate_ln_kernel<<<BATCH, blk>>>(p_mtc, p_ctx1, W_gate, b_gate, ln_s, ln_b, p_fmti, 0);
    gate_ln_kernel<<<N_ENT, blk>>>(p_eic, p_ctx2, W_gate, b_gate, ln_s, ln_b, p_feit, 1);
    gate_ln_kernel<<<BATCH, blk>>>(p_mic, p_ctx3, W_gate, b_gate, ln_s, ln_b, p_fmit, 0);

    // final score
    score_kernel<<<dim3(N_ENT / 64, BATCH / 64), blk>>>(p_fmti, p_feti, p_fmit, p_feit, out);
}

// round 8
// speedup vs baseline: 1.0944x; 1.0140x over previous
#include <cuda_runtime.h>
#include <math.h>
#include <stdint.h>

#define N_ENT 1024
#define BATCH 128
#define T_TOK 64
#define P_TOK 49
#define D_IN 768
#define H_DIM 512
#define N_EXP 8

// ----------------------------- static scratch ------------------------------
__device__ float g_etc[N_ENT * H_DIM];
__device__ float g_eic[N_ENT * H_DIM];
__device__ float g_mtc[BATCH * H_DIM];
__device__ float g_mic[BATCH * H_DIM];
__device__ float g_ett[N_ENT * T_TOK * H_DIM];
__device__ float g_eit[N_ENT * P_TOK * H_DIM];
__device__ float g_mtt[BATCH * T_TOK * H_DIM];
__device__ float g_mit[BATCH * P_TOK * H_DIM];

__device__ float g_eti_m[N_ENT * 50 * H_DIM];
__device__ float g_mti_m[BATCH * 50 * H_DIM];
__device__ float g_eit_m[N_ENT * 65 * H_DIM];
__device__ float g_mit_m[BATCH * 65 * H_DIM];

__device__ int2   g_eidx[4][N_ENT];
__device__ float2 g_ew[4][N_ENT];

__device__ float g_ctx0[N_ENT * H_DIM];
__device__ float g_ctx1[BATCH * H_DIM];
__device__ float g_ctx2[N_ENT * H_DIM];
__device__ float g_ctx3[BATCH * H_DIM];

__device__ float g_fe_ti[N_ENT * H_DIM];
__device__ float g_fm_ti[BATCH * H_DIM];
__device__ float g_fe_it[N_ENT * H_DIM];
__device__ float g_fm_it[BATCH * H_DIM];

__device__ float g_wc_text[D_IN * N_EXP];
__device__ float g_wc_img[D_IN * N_EXP];
__device__ float g_bterm[2 * N_EXP];

// ------------------------------ tf32 helpers -------------------------------
__device__ __forceinline__ void split_tf32(float x, uint32_t& hi, uint32_t& lo)
{
    asm("cvt.rna.tf32.f32 %0, %1;" : "=r"(hi) : "f"(x));
    float r = x - __uint_as_float(hi);
    asm("cvt.rna.tf32.f32 %0, %1;" : "=r"(lo) : "f"(r));
}

__device__ __forceinline__ void mma8(float* c, const uint32_t* a, const uint32_t* b)
{
    asm volatile(
        "mma.sync.aligned.m16n8k8.row.col.f32.tf32.tf32.f32 "
        "{%0,%1,%2,%3}, {%4,%5,%6,%7}, {%8,%9}, {%0,%1,%2,%3};"
        : "+f"(c[0]), "+f"(c[1]), "+f"(c[2]), "+f"(c[3])
        : "r"(a[0]), "r"(a[1]), "r"(a[2]), "r"(a[3]), "r"(b[0]), "r"(b[1]));
}

#define AS_STR 20
#define BS_STR 136   // 136 mod 32 == 8 -> conflict-free B fragment loads

// ----------------- proj (3xTF32): C[M,512]=A[M,768]@W+bias -----------------
// Block 128x128, BK=16, DOUBLE-buffered smem (1 barrier per K tile),
// conflict-free strides.
#define P_ASZ (128 * AS_STR)
#define P_BSZ (16 * BS_STR)
#define P_SMEM_BYTES ((2 * P_ASZ * 2 + 2 * P_BSZ * 2) * 4)

__global__ __launch_bounds__(256) void proj_tc(
    const float* __restrict__ A, const float* __restrict__ W,
    const float* __restrict__ bias, float* __restrict__ C, int M)
{
    extern __shared__ uint32_t dyn[];
    uint32_t* AsH = dyn;                    // [2][P_ASZ]
    uint32_t* AsL = AsH + 2 * P_ASZ;
    uint32_t* BsH = AsL + 2 * P_ASZ;        // [2][P_BSZ]
    uint32_t* BsL = BsH + 2 * P_BSZ;

    const int tid = threadIdx.x;
    const int row0 = blockIdx.x * 128;
    const int col0 = blockIdx.y * 128;
    const int warp = tid >> 5, lane = tid & 31;
    const int wm = warp >> 2, wn = warp & 3;
    const int gid = lane >> 2, tig = lane & 3;

    const int ar  = tid >> 2;
    const int ac4 = (tid & 3) * 4;
    const int bk  = tid >> 5;
    const int bc4 = (tid & 31) * 4;

    float acc[4][4][4];
#pragma unroll
    for (int a = 0; a < 4; a++)
#pragma unroll
        for (int b = 0; b < 4; b++)
#pragma unroll
            for (int c = 0; c < 4; c++) acc[a][b][c] = 0.f;

    float4 pa[2], pb[2];
    const float* Abase = A + (size_t)row0 * D_IN;

    auto load_tiles = [&](int k0) {
        pa[0] = *(const float4*)(Abase + (size_t)ar * D_IN + k0 + ac4);
        pa[1] = *(const float4*)(Abase + (size_t)(ar + 64) * D_IN + k0 + ac4);
        pb[0] = *(const float4*)(W + (size_t)(k0 + bk) * H_DIM + col0 + bc4);
        pb[1] = *(const float4*)(W + (size_t)(k0 + bk + 8) * H_DIM + col0 + bc4);
    };
    auto store_tiles = [&](int buf) {
        uint32_t* aH = AsH + buf * P_ASZ; uint32_t* aL = AsL + buf * P_ASZ;
        uint32_t* bH = BsH + buf * P_BSZ; uint32_t* bL = BsL + buf * P_BSZ;
#pragma unroll
        for (int p = 0; p < 2; p++) {
            float v[4] = {pa[p].x, pa[p].y, pa[p].z, pa[p].w};
            uint4 h, l;
            split_tf32(v[0], h.x, l.x); split_tf32(v[1], h.y, l.y);
            split_tf32(v[2], h.z, l.z); split_tf32(v[3], h.w, l.w);
            int base = (ar + p * 64) * AS_STR + ac4;
            *(uint4*)&aH[base] = h; *(uint4*)&aL[base] = l;

            float u[4] = {pb[p].x, pb[p].y, pb[p].z, pb[p].w};
            split_tf32(u[0], h.x, l.x); split_tf32(u[1], h.y, l.y);
            split_tf32(u[2], h.z, l.z); split_tf32(u[3], h.w, l.w);
            int bbase = (bk + p * 8) * BS_STR + bc4;
            *(uint4*)&bH[bbase] = h; *(uint4*)&bL[bbase] = l;
        }
    };

    load_tiles(0);
    store_tiles(0);
    __syncthreads();

    const int NKB = D_IN / 16;
    for (int kb = 0; kb < NKB; kb++) {
        if (kb + 1 < NKB) load_tiles((kb + 1) * 16);
        const int cur = kb & 1;
        const uint32_t* aH = AsH + cur * P_ASZ; const uint32_t* aL = AsL + cur * P_ASZ;
        const uint32_t* bH = BsH + cur * P_BSZ; const uint32_t* bL = BsL + cur * P_BSZ;
#pragma unroll
        for (int kk = 0; kk < 16; kk += 8) {
            uint32_t ah[4][4], al[4][4], bh[4][2], bl[4][2];
#pragma unroll
            for (int mt = 0; mt < 4; mt++) {
                int b0 = (wm * 64 + mt * 16 + gid) * AS_STR + kk + tig;
                ah[mt][0] = aH[b0];     ah[mt][1] = aH[b0 + 8 * AS_STR];
                ah[mt][2] = aH[b0 + 4]; ah[mt][3] = aH[b0 + 8 * AS_STR + 4];
                al[mt][0] = aL[b0];     al[mt][1] = aL[b0 + 8 * AS_STR];
                al[mt][2] = aL[b0 + 4]; al[mt][3] = aL[b0 + 8 * AS_STR + 4];
            }
#pragma unroll
            for (int nt = 0; nt < 4; nt++) {
                int b0 = (kk + tig) * BS_STR + wn * 32 + nt * 8 + gid;
                bh[nt][0] = bH[b0]; bh[nt][1] = bH[b0 + 4 * BS_STR];
                bl[nt][0] = bL[b0]; bl[nt][1] = bL[b0 + 4 * BS_STR];
            }
#pragma unroll
            for (int mt = 0; mt < 4; mt++)
#pragma unroll
                for (int nt = 0; nt < 4; nt++) mma8(acc[mt][nt], ah[mt], bh[nt]);
#pragma unroll
            for (int mt = 0; mt < 4; mt++)
#pragma unroll
                for (int nt = 0; nt < 4; nt++) mma8(acc[mt][nt], ah[mt], bl[nt]);
#pragma unroll
            for (int mt = 0; mt < 4; mt++)
#pragma unroll
                for (int nt = 0; nt < 4; nt++) mma8(acc[mt][nt], al[mt], bh[nt]);
        }
        if (kb + 1 < NKB) store_tiles((kb + 1) & 1);
        __syncthreads();
    }

#pragma unroll
    for (int mt = 0; mt < 4; mt++) {
        int m = row0 + wm * 64 + mt * 16 + gid;
#pragma unroll
        for (int nt = 0; nt < 4; nt++) {
            int n = col0 + wn * 32 + nt * 8 + tig * 2;
            float2 bv = *(const float2*)(bias + n);
            *(float2*)(C + (size_t)m * H_DIM + n) =
                make_float2(acc[mt][nt][0] + bv.x, acc[mt][nt][1] + bv.y);
            *(float2*)(C + (size_t)(m + 8) * H_DIM + n) =
                make_float2(acc[mt][nt][2] + bv.x, acc[mt][nt][3] + bv.y);
        }
    }
}

// ------- MoE (3xTF32): out = x @ (w0*We[e0]+w1*We[e1]) + combined bias ------
template<int WM>
__global__ __launch_bounds__(256) void moe_tc(
    const float* __restrict__ cls, const float* __restrict__ tok, int S,
    const float* __restrict__ We, const float* __restrict__ be,
    const int2* __restrict__ eidx, const float2* __restrict__ ew,
    float* __restrict__ out)
{
    constexpr int BM = WM * 32;
    constexpr int PF = (BM * 4 + 255) / 256;
    constexpr int ASZ = BM * AS_STR;
    constexpr int BSZ = 16 * BS_STR;

    extern __shared__ uint32_t dyn[];
    uint32_t* AsH = dyn;
    uint32_t* AsL = AsH + 2 * ASZ;
    uint32_t* BsH = AsL + 2 * ASZ;
    uint32_t* BsL = BsH + 2 * BSZ;

    const int i = blockIdx.z;
    const int col0 = blockIdx.x * 128;
    const int2 e = eidx[i];
    const float2 w = ew[i];
    const float* W0 = We + (size_t)e.x * H_DIM * H_DIM;
    const float* W1 = We + (size_t)e.y * H_DIM * H_DIM;

    const int tid = threadIdx.x;
    const int warp = tid >> 5, lane = tid & 31;
    const int wm = warp >> 2, wn = warp & 3;
    const int gid = lane >> 2, tig = lane & 3;
    const int bk = tid >> 5, bc4 = (tid & 31) * 4;

    float acc[WM][4][4];
#pragma unroll
    for (int a = 0; a < WM; a++)
#pragma unroll
        for (int b = 0; b < 4; b++)
#pragma unroll
            for (int c = 0; c < 4; c++) acc[a][b][c] = 0.f;

    float4 pa[PF], pb[2];

    auto load_tiles = [&](int k0) {
#pragma unroll
        for (int p = 0; p < PF; p++) {
            int idx = p * 256 + tid;
            float4 v = make_float4(0.f, 0.f, 0.f, 0.f);
            if (idx < BM * 4) {
                int t = idx >> 2;
                if (t < S) {
                    const float* rp = (t == 0)
                        ? (cls + (size_t)i * H_DIM)
                        : (tok + ((size_t)i * (S - 1) + (t - 1)) * H_DIM);
                    v = *(const float4*)(rp + k0 + (idx & 3) * 4);
                }
            }
            pa[p] = v;
        }
#pragma unroll
        for (int p = 0; p < 2; p++) {
            size_t off = (size_t)(k0 + bk + p * 8) * H_DIM + col0 + bc4;
            float4 v0 = *(const float4*)(W0 + off);
            float4 v1 = *(const float4*)(W1 + off);
            pb[p] = make_float4(w.x * v0.x + w.y * v1.x, w.x * v0.y + w.y * v1.y,
                                w.x * v0.z + w.y * v1.z, w.x * v0.w + w.y * v1.w);
        }
    };
    auto store_tiles = [&](int buf) {
        uint32_t* aH = AsH + buf * ASZ; uint32_t* aL = AsL + buf * ASZ;
        uint32_t* bH = BsH + buf * BSZ; uint32_t* bL = BsL + buf * BSZ;
#pragma unroll
        for (int p = 0; p < PF; p++) {
            int idx = p * 256 + tid;
            if (idx < BM * 4) {
                float v[4] = {pa[p].x, pa[p].y, pa[p].z, pa[p].w};
                uint4 h, l;
                split_tf32(v[0], h.x, l.x); split_tf32(v[1], h.y, l.y);
                split_tf32(v[2], h.z, l.z); split_tf32(v[3], h.w, l.w);
                int base = (idx >> 2) * AS_STR + (idx & 3) * 4;
                *(uint4*)&aH[base] = h; *(uint4*)&aL[base] = l;
            }
        }
#pragma unroll
        for (int p = 0; p < 2; p++) {
            float u[4] = {pb[p].x, pb[p].y, pb[p].z, pb[p].w};
            uint4 h, l;
            split_tf32(u[0], h.x, l.x); split_tf32(u[1], h.y, l.y);
            split_tf32(u[2], h.z, l.z); split_tf32(u[3], h.w, l.w);
            int bbase = (bk + p * 8) * BS_STR + bc4;
            *(uint4*)&bH[bbase] = h; *(uint4*)&bL[bbase] = l;
        }
    };

    load_tiles(0);
    store_tiles(0);
    __syncthreads();

    const int NKB = H_DIM / 16;
    for (int kb = 0; kb < NKB; kb++) {
        if (kb + 1 < NKB) load_tiles((kb + 1) * 16);
        const int cur = kb & 1;
        const uint32_t* aH = AsH + cur * ASZ; const uint32_t* aL = AsL + cur * ASZ;
        const uint32_t* bH = BsH + cur * BSZ; const uint32_t* bL = BsL + cur * BSZ;
#pragma unroll
        for (int kk = 0; kk < 16; kk += 8) {
            uint32_t ah[WM][4], al[WM][4], bh[4][2], bl[4][2];
#pragma unroll
            for (int mt = 0; mt < WM; mt++) {
                int b0 = (wm * WM * 16 + mt * 16 + gid) * AS_STR + kk + tig;
                ah[mt][0] = aH[b0];     ah[mt][1] = aH[b0 + 8 * AS_STR];
                ah[mt][2] = aH[b0 + 4]; ah[mt][3] = aH[b0 + 8 * AS_STR + 4];
                al[mt][0] = aL[b0];     al[mt][1] = aL[b0 + 8 * AS_STR];
                al[mt][2] = aL[b0 + 4]; al[mt][3] = aL[b0 + 8 * AS_STR + 4];
            }
#pragma unroll
            for (int nt = 0; nt < 4; nt++) {
                int b0 = (kk + tig) * BS_STR + wn * 32 + nt * 8 + gid;
                bh[nt][0] = bH[b0]; bh[nt][1] = bH[b0 + 4 * BS_STR];
                bl[nt][0] = bL[b0]; bl[nt][1] = bL[b0 + 4 * BS_STR];
            }
#pragma unroll
            for (int mt = 0; mt < WM; mt++)
#pragma unroll
                for (int nt = 0; nt < 4; nt++) mma8(acc[mt][nt], ah[mt], bh[nt]);
#pragma unroll
            for (int mt = 0; mt < WM; mt++)
#pragma unroll
                for (int nt = 0; nt < 4; nt++) mma8(acc[mt][nt], ah[mt], bl[nt]);
#pragma unroll
            for (int mt = 0; mt < WM; mt++)
#pragma unroll
                for (int nt = 0; nt < 4; nt++) mma8(acc[mt][nt], al[mt], bh[nt]);
        }
        if (kb + 1 < NKB) store_tiles((kb + 1) & 1);
        __syncthreads();
    }

#pragma unroll
    for (int mt = 0; mt < WM; mt++) {
        int t = wm * WM * 16 + mt * 16 + gid;
#pragma unroll
        for (int nt = 0; nt < 4; nt++) {
            int n = col0 + wn * 32 + nt * 8 + tig * 2;
            float b0 = w.x * be[e.x * H_DIM + n]     + w.y * be[e.y * H_DIM + n];
            float b1 = w.x * be[e.x * H_DIM + n + 1] + w.y * be[e.y * H_DIM + n + 1];
            if (t < S)
                *(float2*)(out + ((size_t)i * S + t) * H_DIM + n) =
                    make_float2(acc[mt][nt][0] + b0, acc[mt][nt][1] + b1);
            if (t + 8 < S)
                *(float2*)(out + ((size_t)i * S + t + 8) * H_DIM + n) =
                    make_float2(acc[mt][nt][2] + b0, acc[mt][nt][3] + b1);
        }
    }
}

// --------------------- router weight folding (fp32-exact) ------------------
__global__ void combine_w_kernel(const float* __restrict__ Wt, const float* __restrict__ Wi,
                                 const float* __restrict__ Wr,
                                 float* __restrict__ WcT, float* __restrict__ WcI)
{
    int idx = blockIdx.x * blockDim.x + threadIdx.x;
    if (idx >= D_IN * N_EXP) return;
    int k = idx >> 3, e = idx & 7;
    float st = 0.f, si = 0.f;
    for (int h = 0; h < H_DIM; h++) {
        float wr = Wr[h * N_EXP + e];
        st += Wt[(size_t)k * H_DIM + h] * wr;
        si += Wi[(size_t)k * H_DIM + h] * wr;
    }
    WcT[idx] = st;
    WcI[idx] = si;
}

__global__ void bterm_kernel(const float* __restrict__ bt, const float* __restrict__ bi,
                             const float* __restrict__ Wr, const float* __restrict__ br,
                             float* __restrict__ bterm)
{
    int e = threadIdx.x;
    if (e < N_EXP) {
        float sA = 0.f, sB = 0.f;
        for (int h = 0; h < H_DIM; h++) {
            float wr = Wr[h * N_EXP + e];
            sA += (bi[h] + 64.f * bt[h]) * wr;   // y = [img cls, 64 text tokens]
            sB += (bt[h] + 49.f * bi[h]) * wr;   // y = [text cls, 49 img tokens]
        }
        bterm[e]         = sA / 65.f + br[e];
        bterm[N_EXP + e] = sB / 50.f + br[e];
    }
}

// -------- router: stage1 bandwidth token-sum (float4), stage2 logits -------
__global__ __launch_bounds__(256) void router2_kernel(
    const float* __restrict__ cls, const float* __restrict__ tok, int Sm1,
    const float* __restrict__ WcCls, const float* __restrict__ WcTok,
    const float* __restrict__ bt,
    int2* __restrict__ eidx, float2* __restrict__ ew)
{
    const int i = blockIdx.x, tid = threadIdx.x;
    __shared__ float sumtok[D_IN];
    __shared__ float red[8][N_EXP];
    __shared__ float logits[N_EXP];

    if (tid < 192) {
        const float4* tp = (const float4*)(tok + (size_t)i * Sm1 * D_IN) + tid;
        float4 s0 = make_float4(0.f, 0.f, 0.f, 0.f), s1 = s0, s2 = s0, s3 = s0;
        int t = 0;
        for (; t + 4 <= Sm1; t += 4) {
            float4 a = tp[(size_t)(t + 0) * 192];
            float4 b = tp[(size_t)(t + 1) * 192];
            float4 c = tp[(size_t)(t + 2) * 192];
            float4 d = tp[(size_t)(t + 3) * 192];
            s0.x += a.x; s0.y += a.y; s0.z += a.z; s0.w += a.w;
            s1.x += b.x; s1.y += b.y; s1.z += b.z; s1.w += b.w;
            s2.x += c.x; s2.y += c.y; s2.z += c.z; s2.w += c.w;
            s3.x += d.x; s3.y += d.y; s3.z += d.z; s3.w += d.w;
        }
        for (; t < Sm1; t++) {
            float4 a = tp[(size_t)t * 192];
            s0.x += a.x; s0.y += a.y; s0.z += a.z; s0.w += a.w;
        }
        float4 s = make_float4(s0.x + s1.x + s2.x + s3.x, s0.y + s1.y + s2.y + s3.y,
                               s0.z + s1.z + s2.z + s3.z, s0.w + s1.w + s2.w + s3.w);
        *(float4*)&sumtok[tid * 4] = s;
    }
    __syncthreads();

    const int warp = tid >> 5, lane = tid & 31;
    {
        float part[N_EXP];
#pragma unroll
        for (int e = 0; e < N_EXP; e++) part[e] = 0.f;
        for (int c = tid; c < D_IN; c += 256) {
            float cl = cls[(size_t)i * D_IN + c];
            float s = sumtok[c];
#pragma unroll
            for (int e = 0; e < N_EXP; e++)
                part[e] += cl * WcCls[c * N_EXP + e] + s * WcTok[c * N_EXP + e];
        }
#pragma unroll
        for (int o = 16; o; o >>= 1)
#pragma unroll
            for (int e = 0; e < N_EXP; e++)
                part[e] += __shfl_down_sync(0xffffffffu, part[e], o);
        if (lane == 0)
#pragma unroll
            for (int e = 0; e < N_EXP; e++) red[warp][e] = part[e];
    }
    __syncthreads();
    if (tid < N_EXP) {
        float l = 0.f;
        for (int wq = 0; wq < 8; wq++) l += red[wq][tid];
        logits[tid] = l / (float)(Sm1 + 1) + bt[tid];
    }
    __syncthreads();
    if (tid == 0) {
        int b0 = 0;
        for (int e = 1; e < N_EXP; e++)
            if (logits[e] > logits[b0]) b0 = e;
        int b1 = (b0 == 0) ? 1 : 0;
        for (int e = 0; e < N_EXP; e++)
            if (e != b0 && logits[e] > logits[b1]) b1 = e;
        float e1v = expf(logits[b1] - logits[b0]);
        float inv = 1.0f / (1.0f + e1v);
        eidx[i] = make_int2(b0, b1);
        ew[i] = make_float2(inv, e1v * inv);
    }
}

// ---------------------- cross attention (vectorized) -----------------------
__global__ __launch_bounds__(256) void cross_kernel(
    const float* __restrict__ moe_out, int S, float* __restrict__ ctx)
{
    const int i = blockIdx.x;
    __shared__ float4 cls4[H_DIM / 4];
    __shared__ float prob[64];
    const int tid = threadIdx.x;
    const float* base = moe_out + (size_t)i * S * H_DIM;

    if (tid < H_DIM / 4) cls4[tid] = ((const float4*)base)[tid];
    __syncthreads();

    const int nt = S - 1;
    const int warp = tid >> 5, lane = tid & 31;
    for (int s = warp; s < nt; s += 8) {
        const float4* tr = (const float4*)(base + (size_t)(s + 1) * H_DIM);
        float p = 0.f;
#pragma unroll
        for (int q = 0; q < 4; q++) {
            float4 a = cls4[lane + 32 * q];
            float4 b = tr[lane + 32 * q];
            p += a.x * b.x + a.y * b.y + a.z * b.z + a.w * b.w;
        }
#pragma unroll
        for (int o = 16; o; o >>= 1) p += __shfl_down_sync(0xffffffffu, p, o);
        if (lane == 0) prob[s] = p;
    }
    __syncthreads();

    if (tid == 0) {
        float mx = -1e30f;
        for (int s = 0; s < nt; s++) mx = fmaxf(mx, prob[s]);
        float sum = 0.f;
        for (int s = 0; s < nt; s++) { float e = expf(prob[s] - mx); prob[s] = e; sum += e; }
        float inv = 1.0f / sum;
        for (int s = 0; s < nt; s++) prob[s] *= inv;
    }
    __syncthreads();

    float2 acc = make_float2(0.f, 0.f);
    const float2* b2 = (const float2*)(base + H_DIM) + tid;
#pragma unroll 4
    for (int s = 0; s < nt; s++) {
        float2 v = b2[(size_t)s * (H_DIM / 2)];
        float pw = prob[s];
        acc.x += pw * v.x; acc.y += pw * v.y;
    }
    ((float2*)(ctx + (size_t)i * H_DIM))[tid] = acc;
}

// --------------------------- gate + residual + LN ---------------------------
__global__ __launch_bounds__(256) void gate_ln_kernel(
    const float* __restrict__ ori, const float* __restrict__ ctx,
    const float* __restrict__ Wg, const float* __restrict__ bg,
    const float* __restrict__ ls, const float* __restrict__ lb,
    float* __restrict__ out, int gate_from_ctx)
{
    const int i = blockIdx.x;
    __shared__ float v[H_DIM];
    __shared__ float red[256];
    const int tid = threadIdx.x;
    const float* orow = ori + (size_t)i * H_DIM;
    const float* crow = ctx + (size_t)i * H_DIM;

    float p = 0.f;
    for (int c = tid; c < H_DIM; c += 256) {
        float gs = gate_from_ctx ? crow[c] : orow[c];
        p += gs * Wg[c];
    }
    red[tid] = p; __syncthreads();
    for (int o = 128; o; o >>= 1) { if (tid < o) red[tid] += red[tid + o]; __syncthreads(); }
    float gate = tanhf(red[0] + bg[0]);
    __syncthreads();

    float sum = 0.f;
    for (int c = tid; c < H_DIM; c += 256) {
        float val = orow[c] * gate + crow[c];
        v[c] = val; sum += val;
    }
    red[tid] = sum; __syncthreads();
    for (int o = 128; o; o >>= 1) { if (tid < o) red[tid] += red[tid + o]; __syncthreads(); }
    float mean = red[0] / (float)H_DIM;
    __syncthreads();

    float var = 0.f;
    for (int c = tid; c < H_DIM; c += 256) { float d = v[c] - mean; var += d * d; }
    red[tid] = var; __syncthreads();
    for (int o = 128; o; o >>= 1) { if (tid < o) red[tid] += red[tid + o]; __syncthreads(); }
    float rstd = rsqrtf(red[0] / (float)H_DIM + 1e-5f);

    for (int c = tid; c < H_DIM; c += 256)
        out[(size_t)i * H_DIM + c] = (v[c] - mean) * rstd * ls[c] + lb[c];
}

// -------------------------------- final score -------------------------------
__global__ __launch_bounds__(256) void score_kernel(
    const float* __restrict__ mti, const float* __restrict__ eti,
    const float* __restrict__ mit, const float* __restrict__ eit,
    float* __restrict__ out)
{
    __shared__ float As[8][64];
    __shared__ float Bs[8][64];
    const int n0 = blockIdx.x * 64;
    const int b0 = blockIdx.y * 64;
    const int tid = threadIdx.x;
    const int tx = tid & 15, ty = tid >> 4;
    const int lrow = tid >> 2, lcol = (tid & 3) * 2;

    float acc[4][4];
#pragma unroll
    for (int q = 0; q < 4; q++)
#pragma unroll
        for (int r = 0; r < 4; r++) acc[q][r] = 0.f;

#pragma unroll
    for (int pass = 0; pass < 2; pass++) {
        const float* A = pass ? mit : mti;
        const float* B = pass ? eit : eti;
        for (int k0 = 0; k0 < H_DIM; k0 += 8) {
            float2 av = *(const float2*)(A + (size_t)(b0 + lrow) * H_DIM + k0 + lcol);
            As[lcol][lrow] = av.x; As[lcol + 1][lrow] = av.y;
            float2 bv = *(const float2*)(B + (size_t)(n0 + lrow) * H_DIM + k0 + lcol);
            Bs[lcol][lrow] = bv.x; Bs[lcol + 1][lrow] = bv.y;
            __syncthreads();
#pragma unroll
            for (int k = 0; k < 8; k++) {
                float a[4], b[4];
#pragma unroll
                for (int q = 0; q < 4; q++) a[q] = As[k][ty * 4 + q];
#pragma unroll
                for (int q = 0; q < 4; q++) b[q] = Bs[k][tx * 4 + q];
#pragma unroll
                for (int q = 0; q < 4; q++)
#pragma unroll
                    for (int r = 0; r < 4; r++) acc[q][r] += a[q] * b[r];
            }
            __syncthreads();
        }
    }
#pragma unroll
    for (int q = 0; q < 4; q++)
#pragma unroll
        for (int r = 0; r < 4; r++)
            out[(size_t)(b0 + ty * 4 + q) * N_ENT + (n0 + tx * 4 + r)] = 0.5f * acc[q][r];
}

// ---------------------------------- launch ----------------------------------
extern "C" void kernel_launch(void* const* d_in, const int* in_sizes, int n_in,
                              void* d_out, int out_size)
{
    const float* etc_in = (const float*)d_in[0];
    const float* ett_in = (const float*)d_in[1];
    const float* mtc_in = (const float*)d_in[2];
    const float* mtt_in = (const float*)d_in[3];
    const float* eic_in = (const float*)d_in[4];
    const float* eit_in = (const float*)d_in[5];
    const float* mic_in = (const float*)d_in[6];
    const float* mit_in = (const float*)d_in[7];
    const float* W_text = (const float*)d_in[8];
    const float* b_text = (const float*)d_in[9];
    const float* W_img  = (const float*)d_in[10];
    const float* b_img  = (const float*)d_in[11];
    const float* W_gate = (const float*)d_in[12];
    const float* b_gate = (const float*)d_in[13];
    const float* ln_s   = (const float*)d_in[14];
    const float* ln_b   = (const float*)d_in[15];
    const float* W_rout = (const float*)d_in[16];
    const float* b_rout = (const float*)d_in[17];
    const float* W_exp  = (const float*)d_in[18];
    const float* b_exp  = (const float*)d_in[19];
    float* out = (float*)d_out;

    float *p_etc, *p_eic, *p_mtc, *p_mic, *p_ett, *p_eit, *p_mtt, *p_mit;
    float *p_etim, *p_mtim, *p_eitm, *p_mitm;
    float *p_ctx0, *p_ctx1, *p_ctx2, *p_ctx3;
    float *p_feti, *p_fmti, *p_feit, *p_fmit;
    float *p_wct, *p_wci, *p_bt;
    int2* p_eidx; float2* p_ew;
    cudaGetSymbolAddress((void**)&p_etc, g_etc);
    cudaGetSymbolAddress((void**)&p_eic, g_eic);
    cudaGetSymbolAddress((void**)&p_mtc, g_mtc);
    cudaGetSymbolAddress((void**)&p_mic, g_mic);
    cudaGetSymbolAddress((void**)&p_ett, g_ett);
    cudaGetSymbolAddress((void**)&p_eit, g_eit);
    cudaGetSymbolAddress((void**)&p_mtt, g_mtt);
    cudaGetSymbolAddress((void**)&p_mit, g_mit);
    cudaGetSymbolAddress((void**)&p_etim, g_eti_m);
    cudaGetSymbolAddress((void**)&p_mtim, g_mti_m);
    cudaGetSymbolAddress((void**)&p_eitm, g_eit_m);
    cudaGetSymbolAddress((void**)&p_mitm, g_mit_m);
    cudaGetSymbolAddress((void**)&p_ctx0, g_ctx0);
    cudaGetSymbolAddress((void**)&p_ctx1, g_ctx1);
    cudaGetSymbolAddress((void**)&p_ctx2, g_ctx2);
    cudaGetSymbolAddress((void**)&p_ctx3, g_ctx3);
    cudaGetSymbolAddress((void**)&p_feti, g_fe_ti);
    cudaGetSymbolAddress((void**)&p_fmti, g_fm_ti);
    cudaGetSymbolAddress((void**)&p_feit, g_fe_it);
    cudaGetSymbolAddress((void**)&p_fmit, g_fm_it);
    cudaGetSymbolAddress((void**)&p_wct, g_wc_text);
    cudaGetSymbolAddress((void**)&p_wci, g_wc_img);
    cudaGetSymbolAddress((void**)&p_bt, g_bterm);
    cudaGetSymbolAddress((void**)&p_eidx, g_eidx);
    cudaGetSymbolAddress((void**)&p_ew,   g_ew);

    // opt-in dynamic smem for double-buffered GEMMs
    constexpr int moe2_smem = (2 * 64 * AS_STR * 2 + 2 * 16 * BS_STR * 2) * 4;
    constexpr int moe3_smem = (2 * 96 * AS_STR * 2 + 2 * 16 * BS_STR * 2) * 4;
    cudaFuncSetAttribute(proj_tc,   cudaFuncAttributeMaxDynamicSharedMemorySize, P_SMEM_BYTES);
    cudaFuncSetAttribute(moe_tc<2>, cudaFuncAttributeMaxDynamicSharedMemorySize, moe2_smem);
    cudaFuncSetAttribute(moe_tc<3>, cudaFuncAttributeMaxDynamicSharedMemorySize, moe3_smem);

    dim3 blk(256);

    // 1-2: router weight folding
    combine_w_kernel<<<(D_IN * N_EXP + 255) / 256, blk>>>(W_text, W_img, W_rout, p_wct, p_wci);
    bterm_kernel<<<1, 32>>>(b_text, b_img, W_rout, b_rout, p_bt);

    // 3: first big router
    router2_kernel<<<N_ENT, blk>>>(eic_in, ett_in, T_TOK, p_wci, p_wct, p_bt,
                                   p_eidx + 0 * N_ENT, p_ew + 0 * N_ENT);

    // 4: big ett projection — positioned for ncu capture
    proj_tc<<<dim3(N_ENT * T_TOK / 128, 4), blk, P_SMEM_BYTES>>>(ett_in, W_text, b_text, p_ett, N_ENT * T_TOK);

    // remaining routers
    router2_kernel<<<BATCH, blk>>>(mic_in, mtt_in, T_TOK, p_wci, p_wct, p_bt,
                                   p_eidx + 1 * N_ENT, p_ew + 1 * N_ENT);
    router2_kernel<<<N_ENT, blk>>>(etc_in, eit_in, P_TOK, p_wct, p_wci, p_bt + N_EXP,
                                   p_eidx + 2 * N_ENT, p_ew + 2 * N_ENT);
    router2_kernel<<<BATCH, blk>>>(mtc_in, mit_in, P_TOK, p_wct, p_wci, p_bt + N_EXP,
                                   p_eidx + 3 * N_ENT, p_ew + 3 * N_ENT);

    // remaining projections
    proj_tc<<<dim3(N_ENT / 128, 4), blk, P_SMEM_BYTES>>>(etc_in, W_text, b_text, p_etc, N_ENT);
    proj_tc<<<dim3(BATCH / 128, 4), blk, P_SMEM_BYTES>>>(mtc_in, W_text, b_text, p_mtc, BATCH);
    proj_tc<<<dim3(BATCH * T_TOK / 128, 4), blk, P_SMEM_BYTES>>>(mtt_in, W_text, b_text, p_mtt, BATCH * T_TOK);
    proj_tc<<<dim3(N_ENT / 128, 4), blk, P_SMEM_BYTES>>>(eic_in, W_img, b_img, p_eic, N_ENT);
    proj_tc<<<dim3(N_ENT * P_TOK / 128, 4), blk, P_SMEM_BYTES>>>(eit_in, W_img, b_img, p_eit, N_ENT * P_TOK);
    proj_tc<<<dim3(BATCH / 128, 4), blk, P_SMEM_BYTES>>>(mic_in, W_img, b_img, p_mic, BATCH);
    proj_tc<<<dim3(BATCH * P_TOK / 128, 4), blk, P_SMEM_BYTES>>>(mit_in, W_img, b_img, p_mit, BATCH * P_TOK);

    // MoE GEMMs (combined expert pair, 3xTF32)
    moe_tc<2><<<dim3(4, 1, N_ENT), blk, moe2_smem>>>(p_etc, p_eit, 50, W_exp, b_exp,
                                          p_eidx + 0 * N_ENT, p_ew + 0 * N_ENT, p_etim);
    moe_tc<2><<<dim3(4, 1, BATCH), blk, moe2_smem>>>(p_mtc, p_mit, 50, W_exp, b_exp,
                                          p_eidx + 1 * N_ENT, p_ew + 1 * N_ENT, p_mtim);
    moe_tc<3><<<dim3(4, 1, N_ENT), blk, moe3_smem>>>(p_eic, p_ett, 65, W_exp, b_exp,
                                          p_eidx + 2 * N_ENT, p_ew + 2 * N_ENT, p_eitm);
    moe_tc<3><<<dim3(4, 1, BATCH), blk, moe3_smem>>>(p_mic, p_mtt, 65, W_exp, b_exp,
                                          p_eidx + 3 * N_ENT, p_ew + 3 * N_ENT, p_mitm);

    // cross attention
    cross_kernel<<<N_ENT, blk>>>(p_etim, 50, p_ctx0);
    cross_kernel<<<BATCH, blk>>>(p_mtim, 50, p_ctx1);
    cross_kernel<<<N_ENT, blk>>>(p_eitm, 65, p_ctx2);
    cross_kernel<<<BATCH, blk>>>(p_mitm, 65, p_ctx3);

    // gate + residual + LN
    gate_ln_kernel<<<N_ENT, blk>>>(p_etc, p_ctx0, W_gate, b_gate, ln_s, ln_b, p_feti, 1);
    gate_ln_kernel<<<BATCH, blk>>>(p_mtc, p_ctx1, W_gate, b_gate, ln_s, ln_b, p_fmti, 0);
    gate_ln_kernel<<<N_ENT, blk>>>(p_eic, p_ctx2, W_gate, b_gate, ln_s, ln_b, p_feit, 1);
    gate_ln_kernel<<<BATCH, blk>>>(p_mic, p_ctx3, W_gate, b_gate, ln_s, ln_b, p_fmit, 0);

    // final score
    score_kernel<<<dim3(N_ENT / 64, BATCH / 64), blk>>>(p_fmti, p_feti, p_fmit, p_feit, out);
}